// round 14
// baseline (speedup 1.0000x reference)
#include <cuda_runtime.h>
#include <cuda_bf16.h>
#include <cstdint>

#define N_NODES 50000
#define N_EDGES 600000
#define D 128
#define D2 256
#define NLAYERS 5

// ---------------- scratch (static device memory; no allocations) -------------
__device__ float g_h[N_NODES * D];                // layer-0 features (embed)
__device__ float g_z[N_NODES * D];                // GEMM2 output (y2)
__device__ float g_y1[N_NODES * D2];
__device__ __nv_bfloat16 g_zh[N_NODES * D], g_zl[N_NODES * D];   // agg output, pre-split
__device__ float g_bond_tab[NLAYERS * 512 * D];
__device__ int   g_deg[N_NODES];
__device__ int   g_rowptr[N_NODES + 1];
__device__ int   g_woff[N_NODES];
__device__ uint2 g_edge[N_EDGES];                 // {src | combo<<17, w}
__device__ __nv_bfloat16 g_w1h[NLAYERS * D * D2], g_w1l[NLAYERS * D * D2];
__device__ __nv_bfloat16 g_w2h[NLAYERS * D2 * D], g_w2l[NLAYERS * D2 * D];
// per-layer stats slices (zeroed once per replay in embed_kernel)
__device__ float g_stats1[NLAYERS * 2 * D2];
__device__ float g_stats2[NLAYERS * 2 * D];

// ---------------- helpers ----------------------------------------------------
__device__ __forceinline__ uint32_t smem_u32(const void* p) {
    return (uint32_t)__cvta_generic_to_shared(p);
}
__device__ __forceinline__ void ldsm4(uint32_t addr, uint32_t& r0, uint32_t& r1,
                                      uint32_t& r2, uint32_t& r3) {
    asm volatile("ldmatrix.sync.aligned.m8n8.x4.shared.b16 {%0,%1,%2,%3}, [%4];"
                 : "=r"(r0), "=r"(r1), "=r"(r2), "=r"(r3) : "r"(addr));
}
__device__ __forceinline__ void ldsm4t(uint32_t addr, uint32_t& r0, uint32_t& r1,
                                       uint32_t& r2, uint32_t& r3) {
    asm volatile("ldmatrix.sync.aligned.m8n8.x4.trans.shared.b16 {%0,%1,%2,%3}, [%4];"
                 : "=r"(r0), "=r"(r1), "=r"(r2), "=r"(r3) : "r"(addr));
}
__device__ __forceinline__ void mma16816(float* c, const uint32_t* a, const uint32_t* b) {
    asm volatile(
        "mma.sync.aligned.m16n8k16.row.col.f32.bf16.bf16.f32 "
        "{%0,%1,%2,%3}, {%4,%5,%6,%7}, {%8,%9}, {%0,%1,%2,%3};"
        : "+f"(c[0]), "+f"(c[1]), "+f"(c[2]), "+f"(c[3])
        : "r"(a[0]), "r"(a[1]), "r"(a[2]), "r"(a[3]), "r"(b[0]), "r"(b[1]));
}
__device__ __forceinline__ void cp_async16(uint32_t dst, const void* src, int szbytes) {
    asm volatile("cp.async.cg.shared.global [%0], [%1], 16, %2;"
                 :: "r"(dst), "l"(src), "r"(szbytes));
}
__device__ __forceinline__ void cp_commit() { asm volatile("cp.async.commit_group;"); }
__device__ __forceinline__ void cp_wait0() { asm volatile("cp.async.wait_group 0;"); }
__device__ __forceinline__ void cp_wait1() { asm volatile("cp.async.wait_group 1;"); }
__device__ __forceinline__ void split2(float x0, float x1,
                                       __nv_bfloat162& hi, __nv_bfloat162& lo) {
    __nv_bfloat16 h0 = __float2bfloat16_rn(x0);
    __nv_bfloat16 h1 = __float2bfloat16_rn(x1);
    hi = __nv_bfloat162(h0, h1);
    lo = __nv_bfloat162(__float2bfloat16_rn(x0 - __bfloat162float(h0)),
                        __float2bfloat16_rn(x1 - __bfloat162float(h1)));
}

// ---------------- node embedding + all-layer stats zero ----------------------
__global__ void embed_kernel(const int* __restrict__ x,
                             const float* __restrict__ atom_emb) {
    int idx = blockIdx.x * blockDim.x + threadIdx.x;
    if (idx < NLAYERS * 2 * D2) g_stats1[idx] = 0.f;
    if (idx < NLAYERS * 2 * D)  g_stats2[idx] = 0.f;
    int node = idx >> 5, lane = idx & 31;
    if (node >= N_NODES) return;
    const int* xr = x + node * 9;
    float4 acc = make_float4(0.f, 0.f, 0.f, 0.f);
#pragma unroll
    for (int f = 0; f < 9; f++) {
        int v = __ldg(xr + f);
        float4 t = ((const float4*)(atom_emb + (size_t)(f * 64 + v) * D))[lane];
        acc.x += t.x; acc.y += t.y; acc.z += t.z; acc.w += t.w;
    }
    ((float4*)(g_h + (size_t)node * D))[lane] = acc;
}

// ---------------- combined bond table ----------------------------------------
__global__ void bond_table_kernel(const float* __restrict__ bond_emb) {
    int wid = (blockIdx.x * blockDim.x + threadIdx.x) >> 5;
    int lane = threadIdx.x & 31;
    if (wid >= NLAYERS * 512) return;
    int l = wid >> 9, combo = wid & 511;
    int a0 = combo & 7, a1 = (combo >> 3) & 7, a2 = combo >> 6;
    const float* be = bond_emb + (size_t)l * 3 * 8 * D;
    float4 v0 = ((const float4*)(be + a0 * D))[lane];
    float4 v1 = ((const float4*)(be + (8 + a1) * D))[lane];
    float4 v2 = ((const float4*)(be + (16 + a2) * D))[lane];
    float4 s;
    s.x = v0.x + v1.x + v2.x;
    s.y = v0.y + v1.y + v2.y;
    s.z = v0.z + v1.z + v2.z;
    s.w = v0.w + v1.w + v2.w;
    ((float4*)(g_bond_tab + (size_t)wid * D))[lane] = s;
}

// ---------------- CSR build ---------------------------------------------------
__global__ void hist_zero_kernel() {
    int i = blockIdx.x * blockDim.x + threadIdx.x;
    if (i < N_NODES) g_deg[i] = 0;
}
__global__ void hist_kernel(const int* __restrict__ edge_index) {
    int e = blockIdx.x * blockDim.x + threadIdx.x;
    if (e >= N_EDGES) return;
    atomicAdd(&g_deg[__ldg(edge_index + N_EDGES + e)], 1);
}
__global__ void scan_kernel() {
    __shared__ int part[1024];
    const int CH = (N_NODES + 1023) / 1024;
    int t = threadIdx.x;
    int base = t * CH;
    int hi = min(base + CH, N_NODES);
    int s = 0;
    for (int i = base; i < hi; i++) s += g_deg[i];
    part[t] = s;
    __syncthreads();
    for (int off = 1; off < 1024; off <<= 1) {
        int v = (t >= off) ? part[t - off] : 0;
        __syncthreads();
        part[t] += v;
        __syncthreads();
    }
    int run = (t > 0) ? part[t - 1] : 0;
    for (int i = base; i < hi; i++) {
        g_rowptr[i] = run;
        g_woff[i] = run;
        run += g_deg[i];
    }
    if (t == 1023) g_rowptr[N_NODES] = part[1023];
}
__global__ void scatter_kernel(const int* __restrict__ edge_index,
                               const int* __restrict__ edge_attr,
                               const float* __restrict__ edge_weight) {
    int e = blockIdx.x * blockDim.x + threadIdx.x;
    if (e >= N_EDGES) return;
    int s = __ldg(edge_index + e);
    int d = __ldg(edge_index + N_EDGES + e);
    int a0 = __ldg(edge_attr + e * 3 + 0);
    int a1 = __ldg(edge_attr + e * 3 + 1);
    int a2 = __ldg(edge_attr + e * 3 + 2);
    uint32_t combo = (uint32_t)(a0 + (a1 << 3) + (a2 << 6));
    int pos = atomicAdd(&g_woff[d], 1);
    g_edge[pos] = make_uint2((uint32_t)s | (combo << 17),
                             __float_as_uint(__ldg(edge_weight + e)));
}

// ---- CSR aggregation with on-the-fly BN2(prev layer)+relu on gathered rows --
// src = g_h (l==0, identity transform) or g_z = y2(l-1) (use_bn=1).
// z[n] = (1+eps)*f(src[n]) + sum_e relu(f(src[src_e]) + T[combo])*w,
// f(x) = use_bn ? relu(x*sc+sh) : x.  Output written pre-split bf16 hi/lo.
__global__ void agg_kernel(const float* __restrict__ src_feat,
                           const float* __restrict__ eps_p, int l, int use_bn,
                           const float* __restrict__ stats_prev,
                           const float* __restrict__ bng,
                           const float* __restrict__ bnb) {
    __shared__ __align__(16) float s_sc[D], s_sh[D];
    int tid = threadIdx.x;
    if (tid < D) {
        if (use_bn) {
            const float invn = 1.f / (float)N_NODES;
            float m = stats_prev[tid] * invn;
            float var = stats_prev[D + tid] * invn - m * m;
            float sc = bng[tid] * rsqrtf(var + 1e-5f);
            s_sc[tid] = sc;
            s_sh[tid] = bnb[tid] - m * sc;
        } else {
            s_sc[tid] = 1.f;
            s_sh[tid] = 0.f;
        }
    }
    __syncthreads();

    int t = blockIdx.x * blockDim.x + tid;
    int gw = t >> 5;
    int lane = tid & 31;
    if (gw >= N_NODES) return;

    float4 sc4 = ((const float4*)s_sc)[lane];
    float4 sh4 = ((const float4*)s_sh)[lane];
    const float* tab = g_bond_tab + (size_t)l * 512 * D;
    float s = 1.f + __ldg(eps_p + l);

    // seed: (1+eps) * f(own row)
    float4 acc = ((const float4*)(src_feat + (size_t)gw * D))[lane];
    acc.x = fmaf(acc.x, sc4.x, sh4.x);
    acc.y = fmaf(acc.y, sc4.y, sh4.y);
    acc.z = fmaf(acc.z, sc4.z, sh4.z);
    acc.w = fmaf(acc.w, sc4.w, sh4.w);
    if (use_bn) {
        acc.x = fmaxf(acc.x, 0.f); acc.y = fmaxf(acc.y, 0.f);
        acc.z = fmaxf(acc.z, 0.f); acc.w = fmaxf(acc.w, 0.f);
    }
    acc.x *= s; acc.y *= s; acc.z *= s; acc.w *= s;

    int beg = __ldg(&g_rowptr[gw]);
    int end = __ldg(&g_rowptr[gw + 1]);
    for (int e = beg; e < end; e++) {
        uint2 md = __ldg(&g_edge[e]);
        int srcn = md.x & 0x1FFFF;
        int combo = md.x >> 17;
        float w = __uint_as_float(md.y);
        float4 hv = __ldg(((const float4*)(src_feat + (size_t)srcn * D)) + lane);
        hv.x = fmaf(hv.x, sc4.x, sh4.x);
        hv.y = fmaf(hv.y, sc4.y, sh4.y);
        hv.z = fmaf(hv.z, sc4.z, sh4.z);
        hv.w = fmaf(hv.w, sc4.w, sh4.w);
        if (use_bn) {
            hv.x = fmaxf(hv.x, 0.f); hv.y = fmaxf(hv.y, 0.f);
            hv.z = fmaxf(hv.z, 0.f); hv.w = fmaxf(hv.w, 0.f);
        }
        float4 ev = __ldg(((const float4*)(tab + (size_t)combo * D)) + lane);
        acc.x += fmaxf(hv.x + ev.x, 0.f) * w;
        acc.y += fmaxf(hv.y + ev.y, 0.f) * w;
        acc.z += fmaxf(hv.z + ev.z, 0.f) * w;
        acc.w += fmaxf(hv.w + ev.w, 0.f) * w;
    }
    __nv_bfloat162 h0, l0, h1, l1;
    split2(acc.x, acc.y, h0, l0);
    split2(acc.z, acc.w, h1, l1);
    __nv_bfloat162* zh = (__nv_bfloat162*)(g_zh + (size_t)gw * D);
    __nv_bfloat162* zl = (__nv_bfloat162*)(g_zl + (size_t)gw * D);
    zh[lane * 2] = h0; zh[lane * 2 + 1] = h1;
    zl[lane * 2] = l0; zl[lane * 2 + 1] = l1;
}

// ---------------- fp32 -> bf16 hi/lo split (weights preprocess only) ---------
__global__ void split_kernel(const float* __restrict__ src,
                             __nv_bfloat16* __restrict__ dh,
                             __nv_bfloat16* __restrict__ dl, int n4) {
    int i = blockIdx.x * blockDim.x + threadIdx.x;
    if (i >= n4) return;
    float4 v = ((const float4*)src)[i];
    __nv_bfloat162 h0, l0, h1, l1;
    split2(v.x, v.y, h0, l0);
    split2(v.z, v.w, h1, l1);
    ((__nv_bfloat162*)dh)[i * 2]     = h0;
    ((__nv_bfloat162*)dh)[i * 2 + 1] = h1;
    ((__nv_bfloat162*)dl)[i * 2]     = l0;
    ((__nv_bfloat162*)dl)[i * 2 + 1] = l1;
}

// ---------------- common tile geometry ---------------------------------------
#define A_STRIDE 40
#define B_STRIDE 136
#define GBM 128
#define GBN 128
#define GBK 32
#define A_BYTES (GBM * A_STRIDE * 2)
#define B_BYTES (GBK * B_STRIDE * 2)
#define STAGE_BYTES (2 * A_BYTES + 2 * B_BYTES)
#define SMEM_GEMM (2 * STAGE_BYTES)

// ======== GEMM variant 1: all-presplit inputs (A and B bf16 hi/lo, cp.async) =
template <int K, int NOUT>
__global__ __launch_bounds__(256, 2)
void gemm_presplit_kernel(const __nv_bfloat16* __restrict__ Ah_g,
                          const __nv_bfloat16* __restrict__ Al_g,
                          const __nv_bfloat16* __restrict__ Bh_g,
                          const __nv_bfloat16* __restrict__ Bl_g,
                          const float* __restrict__ bias, float* __restrict__ C,
                          float* __restrict__ stats) {
    const int NT = K / GBK;
    extern __shared__ __align__(16) char smem[];
    __shared__ float ssum[GBN], ssq[GBN];

    int tid = threadIdx.x;
    int lane = tid & 31, warp = tid >> 5;
    int wm = warp & 1, wn = warp >> 1;
    int rowBase = blockIdx.y * GBM;
    int colBase = blockIdx.x * GBN;

    if (tid < GBN) { ssum[tid] = 0.f; ssq[tid] = 0.f; }

    float acc[4][4][4];
#pragma unroll
    for (int i = 0; i < 4; i++)
#pragma unroll
        for (int j = 0; j < 4; j++)
#pragma unroll
            for (int q = 0; q < 4; q++) acc[i][j][q] = 0.f;

    auto pA_h = [&](int s) { return (__nv_bfloat16*)(smem + s * STAGE_BYTES); };
    auto pA_l = [&](int s) { return (__nv_bfloat16*)(smem + s * STAGE_BYTES + A_BYTES); };
    auto pB_h = [&](int s) { return (__nv_bfloat16*)(smem + s * STAGE_BYTES + 2 * A_BYTES); };
    auto pB_l = [&](int s) { return (__nv_bfloat16*)(smem + s * STAGE_BYTES + 2 * A_BYTES + B_BYTES); };

    auto LOADS = [&](int kt, int s) {
#pragma unroll
        for (int i = 0; i < 2; i++) {
            int id = tid + i * 256;
            int r = id >> 2, c = (id & 3) * 8;
            int grow = rowBase + r;
            int sz = (grow < N_NODES) ? 16 : 0;
            cp_async16(smem_u32(pA_h(s) + r * A_STRIDE + c),
                       Ah_g + (size_t)grow * K + kt + c, sz);
            cp_async16(smem_u32(pA_l(s) + r * A_STRIDE + c),
                       Al_g + (size_t)grow * K + kt + c, sz);
        }
#pragma unroll
        for (int i = 0; i < 2; i++) {
            int id = tid + i * 256;
            int r = id >> 4, c = (id & 15) * 8;
            cp_async16(smem_u32(pB_h(s) + r * B_STRIDE + c),
                       Bh_g + (size_t)(kt + r) * NOUT + colBase + c, 16);
            cp_async16(smem_u32(pB_l(s) + r * B_STRIDE + c),
                       Bl_g + (size_t)(kt + r) * NOUT + colBase + c, 16);
        }
    };

    int lr = lane & 15;
    int lc = (lane >> 4) << 3;

    LOADS(0, 0);
    cp_commit();

#pragma unroll 1
    for (int t = 0; t < NT; t++) {
        int s = t & 1;
        if (t + 1 < NT) {
            LOADS((t + 1) * GBK, s ^ 1);
            cp_commit();
            cp_wait1();
        } else {
            cp_wait0();
        }
        __syncthreads();

        const __nv_bfloat16* Ahs = pA_h(s);
        const __nv_bfloat16* Als = pA_l(s);
        const __nv_bfloat16* Bhs = pB_h(s);
        const __nv_bfloat16* Bls = pB_l(s);
#pragma unroll
        for (int ks = 0; ks < GBK; ks += 16) {
            uint32_t bh[4][2], bl[4][2];
#pragma unroll
            for (int nb = 0; nb < 2; nb++) {
                int ncol = wn * 32 + nb * 16 + lc;
                uint32_t r0, r1, r2, r3;
                ldsm4t(smem_u32(Bhs + (ks + lr) * B_STRIDE + ncol), r0, r1, r2, r3);
                bh[nb * 2][0] = r0; bh[nb * 2][1] = r1;
                bh[nb * 2 + 1][0] = r2; bh[nb * 2 + 1][1] = r3;
                ldsm4t(smem_u32(Bls + (ks + lr) * B_STRIDE + ncol), r0, r1, r2, r3);
                bl[nb * 2][0] = r0; bl[nb * 2][1] = r1;
                bl[nb * 2 + 1][0] = r2; bl[nb * 2 + 1][1] = r3;
            }
#pragma unroll
            for (int mf = 0; mf < 4; mf++) {
                int mrow = wm * 64 + mf * 16 + lr;
                uint32_t ah[4], al[4];
                ldsm4(smem_u32(Ahs + mrow * A_STRIDE + ks + lc), ah[0], ah[1], ah[2], ah[3]);
                ldsm4(smem_u32(Als + mrow * A_STRIDE + ks + lc), al[0], al[1], al[2], al[3]);
#pragma unroll
                for (int nf = 0; nf < 4; nf++) {
                    mma16816(acc[mf][nf], ah, bh[nf]);
                    mma16816(acc[mf][nf], ah, bl[nf]);
                    mma16816(acc[mf][nf], al, bh[nf]);
                }
            }
        }
        __syncthreads();
    }

    int crow = lane >> 2;
    int ccol = (lane & 3) * 2;
    float bcol8[4][2];
#pragma unroll
    for (int nf = 0; nf < 4; nf++) {
        bcol8[nf][0] = bias[colBase + wn * 32 + nf * 8 + ccol];
        bcol8[nf][1] = bias[colBase + wn * 32 + nf * 8 + ccol + 1];
    }
    float psum[4][2] = {}, psq[4][2] = {};
#pragma unroll
    for (int mf = 0; mf < 4; mf++)
#pragma unroll
        for (int r2 = 0; r2 < 2; r2++) {
            int r = rowBase + wm * 64 + mf * 16 + crow + r2 * 8;
            if (r < N_NODES) {
#pragma unroll
                for (int nf = 0; nf < 4; nf++) {
                    float v0 = acc[mf][nf][r2 * 2 + 0] + bcol8[nf][0];
                    float v1 = acc[mf][nf][r2 * 2 + 1] + bcol8[nf][1];
                    *(float2*)(C + (size_t)r * NOUT + colBase + wn * 32 + nf * 8 + ccol) =
                        make_float2(v0, v1);
                    psum[nf][0] += v0; psq[nf][0] += v0 * v0;
                    psum[nf][1] += v1; psq[nf][1] += v1 * v1;
                }
            }
        }
    __syncthreads();
#pragma unroll
    for (int nf = 0; nf < 4; nf++) {
        int c = wn * 32 + nf * 8 + ccol;
        atomicAdd(&ssum[c],     psum[nf][0]);
        atomicAdd(&ssum[c + 1], psum[nf][1]);
        atomicAdd(&ssq[c],      psq[nf][0]);
        atomicAdd(&ssq[c + 1],  psq[nf][1]);
    }
    __syncthreads();
    if (tid < GBN) {
        atomicAdd(&stats[colBase + tid], ssum[tid]);
        atomicAdd(&stats[NOUT + colBase + tid], ssq[tid]);
    }
}

// ======== GEMM variant 2: fused BN1+relu+split on fp32 A (GEMM2) =============
template <int K, int NOUT>
__global__ __launch_bounds__(256, 2)
void gemm_fused_kernel(const float* __restrict__ A,
                       const __nv_bfloat16* __restrict__ Bh_g,
                       const __nv_bfloat16* __restrict__ Bl_g,
                       const float* __restrict__ bias, float* __restrict__ C,
                       const float* __restrict__ stats_in,
                       const float* __restrict__ bng, const float* __restrict__ bnb,
                       float* __restrict__ stats) {
    const int NT = K / GBK;
    extern __shared__ __align__(16) char smem[];
    __shared__ float ssum[GBN], ssq[GBN];
    __shared__ __align__(16) float s_sc[K], s_sh[K];

    int tid = threadIdx.x;
    int lane = tid & 31, warp = tid >> 5;
    int wm = warp & 1, wn = warp >> 1;
    int rowBase = blockIdx.y * GBM;
    int colBase = blockIdx.x * GBN;

    if (tid < GBN) { ssum[tid] = 0.f; ssq[tid] = 0.f; }

    if (tid < K) {
        const float invn = 1.f / (float)N_NODES;
        float m = stats_in[tid] * invn;
        float var = stats_in[K + tid] * invn - m * m;
        float sc = bng[tid] * rsqrtf(var + 1e-5f);
        s_sc[tid] = sc;
        s_sh[tid] = bnb[tid] - m * sc;
    }
    __syncthreads();

    float acc[4][4][4];
#pragma unroll
    for (int i = 0; i < 4; i++)
#pragma unroll
        for (int j = 0; j < 4; j++)
#pragma unroll
            for (int q = 0; q < 4; q++) acc[i][j][q] = 0.f;

    auto pA_h = [&](int s) { return (__nv_bfloat16*)(smem + s * STAGE_BYTES); };
    auto pA_l = [&](int s) { return (__nv_bfloat16*)(smem + s * STAGE_BYTES + A_BYTES); };
    auto pB_h = [&](int s) { return (__nv_bfloat16*)(smem + s * STAGE_BYTES + 2 * A_BYTES); };
    auto pB_l = [&](int s) { return (__nv_bfloat16*)(smem + s * STAGE_BYTES + 2 * A_BYTES + B_BYTES); };

    int ar  = tid >> 1;
    int acb = (tid & 1) * 16;
    int agrow = rowBase + ar;
    bool arow_ok = (agrow < N_NODES);

    float4 areg[4];

    auto LOAD_A = [&](int kt) {
        if (arow_ok) {
            const float* ap = A + (size_t)agrow * K + kt + acb;
            areg[0] = *(const float4*)(ap + 0);
            areg[1] = *(const float4*)(ap + 4);
            areg[2] = *(const float4*)(ap + 8);
            areg[3] = *(const float4*)(ap + 12);
#pragma unroll
            for (int j = 0; j < 4; j++) {
                float4 sc = *(const float4*)(s_sc + kt + acb + j * 4);
                float4 sh = *(const float4*)(s_sh + kt + acb + j * 4);
                areg[j].x = fmaxf(fmaf(areg[j].x, sc.x, sh.x), 0.f);
                areg[j].y = fmaxf(fmaf(areg[j].y, sc.y, sh.y), 0.f);
                areg[j].z = fmaxf(fmaf(areg[j].z, sc.z, sh.z), 0.f);
                areg[j].w = fmaxf(fmaf(areg[j].w, sc.w, sh.w), 0.f);
            }
        } else {
            float4 z4 = make_float4(0.f, 0.f, 0.f, 0.f);
            areg[0] = z4; areg[1] = z4; areg[2] = z4; areg[3] = z4;
        }
    };
    auto STORE_A = [&](int s) {
        __nv_bfloat16* dh = pA_h(s) + ar * A_STRIDE + acb;
        __nv_bfloat16* dl = pA_l(s) + ar * A_STRIDE + acb;
#pragma unroll
        for (int j = 0; j < 4; j++) {
            __nv_bfloat162 h0, l0, h1, l1;
            split2(areg[j].x, areg[j].y, h0, l0);
            split2(areg[j].z, areg[j].w, h1, l1);
            *(__nv_bfloat162*)(dh + j * 4)     = h0;
            *(__nv_bfloat162*)(dh + j * 4 + 2) = h1;
            *(__nv_bfloat162*)(dl + j * 4)     = l0;
            *(__nv_bfloat162*)(dl + j * 4 + 2) = l1;
        }
    };
    auto LOAD_B = [&](int kt, int s) {
#pragma unroll
        for (int i = 0; i < 2; i++) {
            int id = tid + i * 256;
            int r = id >> 4, c = (id & 15) * 8;
            cp_async16(smem_u32(pB_h(s) + r * B_STRIDE + c),
                       Bh_g + (size_t)(kt + r) * NOUT + colBase + c, 16);
            cp_async16(smem_u32(pB_l(s) + r * B_STRIDE + c),
                       Bl_g + (size_t)(kt + r) * NOUT + colBase + c, 16);
        }
    };

    int lr = lane & 15;
    int lc = (lane >> 4) << 3;

    LOAD_B(0, 0); cp_commit();
    LOAD_A(0);
    STORE_A(0);
    cp_wait0();
    __syncthreads();

    int buf = 0;
#pragma unroll 1
    for (int t = 0; t < NT; t++) {
        if (t + 1 < NT) {
            LOAD_B((t + 1) * GBK, buf ^ 1);
            cp_commit();
            LOAD_A((t + 1) * GBK);
        }

        const __nv_bfloat16* Ahs = pA_h(buf);
        const __nv_bfloat16* Als = pA_l(buf);
        const __nv_bfloat16* Bhs = pB_h(buf);
        const __nv_bfloat16* Bls = pB_l(buf);
#pragma unroll
        for (int ks = 0; ks < GBK; ks += 16) {
            uint32_t bh[4][2], bl[4][2];
#pragma unroll
            for (int nb = 0; nb < 2; nb++) {
                int ncol = wn * 32 + nb * 16 + lc;
                uint32_t r0, r1, r2, r3;
                ldsm4t(smem_u32(Bhs + (ks + lr) * B_STRIDE + ncol), r0, r1, r2, r3);
                bh[nb * 2][0] = r0; bh[nb * 2][1] = r1;
                bh[nb * 2 + 1][0] = r2; bh[nb * 2 + 1][1] = r3;
                ldsm4t(smem_u32(Bls + (ks + lr) * B_STRIDE + ncol), r0, r1, r2, r3);
                bl[nb * 2][0] = r0; bl[nb * 2][1] = r1;
                bl[nb * 2 + 1][0] = r2; bl[nb * 2 + 1][1] = r3;
            }
#pragma unroll
            for (int mf = 0; mf < 4; mf++) {
                int mrow = wm * 64 + mf * 16 + lr;
                uint32_t ah[4], al[4];
                ldsm4(smem_u32(Ahs + mrow * A_STRIDE + ks + lc), ah[0], ah[1], ah[2], ah[3]);
                ldsm4(smem_u32(Als + mrow * A_STRIDE + ks + lc), al[0], al[1], al[2], al[3]);
#pragma unroll
                for (int nf = 0; nf < 4; nf++) {
                    mma16816(acc[mf][nf], ah, bh[nf]);
                    mma16816(acc[mf][nf], ah, bl[nf]);
                    mma16816(acc[mf][nf], al, bh[nf]);
                }
            }
        }

        if (t + 1 < NT) {
            STORE_A(buf ^ 1);
            cp_wait0();
            __syncthreads();
            buf ^= 1;
        }
    }

    int crow = lane >> 2;
    int ccol = (lane & 3) * 2;
    float bcol8[4][2];
#pragma unroll
    for (int nf = 0; nf < 4; nf++) {
        bcol8[nf][0] = bias[colBase + wn * 32 + nf * 8 + ccol];
        bcol8[nf][1] = bias[colBase + wn * 32 + nf * 8 + ccol + 1];
    }
    float psum[4][2] = {}, psq[4][2] = {};
#pragma unroll
    for (int mf = 0; mf < 4; mf++)
#pragma unroll
        for (int r2 = 0; r2 < 2; r2++) {
            int r = rowBase + wm * 64 + mf * 16 + crow + r2 * 8;
            if (r < N_NODES) {
#pragma unroll
                for (int nf = 0; nf < 4; nf++) {
                    float v0 = acc[mf][nf][r2 * 2 + 0] + bcol8[nf][0];
                    float v1 = acc[mf][nf][r2 * 2 + 1] + bcol8[nf][1];
                    *(float2*)(C + (size_t)r * NOUT + colBase + wn * 32 + nf * 8 + ccol) =
                        make_float2(v0, v1);
                    psum[nf][0] += v0; psq[nf][0] += v0 * v0;
                    psum[nf][1] += v1; psq[nf][1] += v1 * v1;
                }
            }
        }
    __syncthreads();
#pragma unroll
    for (int nf = 0; nf < 4; nf++) {
        int c = wn * 32 + nf * 8 + ccol;
        atomicAdd(&ssum[c],     psum[nf][0]);
        atomicAdd(&ssum[c + 1], psum[nf][1]);
        atomicAdd(&ssq[c],      psq[nf][0]);
        atomicAdd(&ssq[c + 1],  psq[nf][1]);
    }
    __syncthreads();
    if (tid < GBN) {
        atomicAdd(&stats[colBase + tid], ssum[tid]);
        atomicAdd(&stats[NOUT + colBase + tid], ssq[tid]);
    }
}

// ------- FINAL output only: BN2(last layer), no relu -------------------------
__global__ void bn_apply_kernel(float* __restrict__ final_out,
                                const float* __restrict__ stats_last,
                                const float* __restrict__ bng,
                                const float* __restrict__ bnb) {
    __shared__ __align__(16) float s_sc[D], s_sh[D];
    int tid = threadIdx.x;
    if (tid < D) {
        const float invn = 1.f / (float)N_NODES;
        float m = stats_last[tid] * invn;
        float var = stats_last[D + tid] * invn - m * m;
        float sc = bng[tid] * rsqrtf(var + 1e-5f);
        s_sc[tid] = sc;
        s_sh[tid] = bnb[tid] - m * sc;
    }
    __syncthreads();
    int idx = blockIdx.x * blockDim.x + tid;
    if (idx >= N_NODES * (D / 4)) return;
    int c4 = idx & 31;
    float4 v = ((const float4*)g_z)[idx];
    float4 sc = ((const float4*)s_sc)[c4];
    float4 sh = ((const float4*)s_sh)[c4];
    v.x = fmaf(v.x, sc.x, sh.x);
    v.y = fmaf(v.y, sc.y, sh.y);
    v.z = fmaf(v.z, sc.z, sh.z);
    v.w = fmaf(v.w, sc.w, sh.w);
    ((float4*)final_out)[idx] = v;
}

// ---------------- launcher ---------------------------------------------------
extern "C" void kernel_launch(void* const* d_in, const int* in_sizes, int n_in,
                              void* d_out, int out_size) {
    const int*   x           = (const int*)d_in[0];
    const int*   edge_index  = (const int*)d_in[1];
    const int*   edge_attr   = (const int*)d_in[2];
    const float* edge_weight = (const float*)d_in[3];
    const float* atom_emb    = (const float*)d_in[4];
    const float* bond_emb    = (const float*)d_in[5];
    const float* W1          = (const float*)d_in[6];
    const float* b1          = (const float*)d_in[7];
    const float* bn1_g       = (const float*)d_in[8];
    const float* bn1_b       = (const float*)d_in[9];
    const float* W2          = (const float*)d_in[10];
    const float* b2          = (const float*)d_in[11];
    const float* eps_p       = (const float*)d_in[12];
    const float* bn_g        = (const float*)d_in[13];
    const float* bn_b        = (const float*)d_in[14];
    float* out = (float*)d_out;

    float *p_h, *p_z, *p_y1, *p_st1, *p_st2;
    __nv_bfloat16 *p_zh, *p_zl, *p_w1h, *p_w1l, *p_w2h, *p_w2l;
    cudaGetSymbolAddress((void**)&p_h,   g_h);
    cudaGetSymbolAddress((void**)&p_z,   g_z);
    cudaGetSymbolAddress((void**)&p_y1,  g_y1);
    cudaGetSymbolAddress((void**)&p_st1, g_stats1);
    cudaGetSymbolAddress((void**)&p_st2, g_stats2);
    cudaGetSymbolAddress((void**)&p_zh,  g_zh);
    cudaGetSymbolAddress((void**)&p_zl,  g_zl);
    cudaGetSymbolAddress((void**)&p_w1h, g_w1h);
    cudaGetSymbolAddress((void**)&p_w1l, g_w1l);
    cudaGetSymbolAddress((void**)&p_w2h, g_w2h);
    cudaGetSymbolAddress((void**)&p_w2l, g_w2l);

    cudaFuncSetAttribute(gemm_presplit_kernel<D, D2>,
                         cudaFuncAttributeMaxDynamicSharedMemorySize, SMEM_GEMM);
    cudaFuncSetAttribute(gemm_fused_kernel<D2, D>,
                         cudaFuncAttributeMaxDynamicSharedMemorySize, SMEM_GEMM);

    const int ELT_BLOCKS = (N_NODES * (D / 4) + 255) / 256;
    const int MB = (N_NODES + GBM - 1) / GBM;
    const int WN4 = NLAYERS * D * D2 / 4;
    const int EB = (N_EDGES + 255) / 256;

    embed_kernel<<<(N_NODES * 32 + 255) / 256, 256>>>(x, atom_emb);
    bond_table_kernel<<<(NLAYERS * 512 * 32 + 255) / 256, 256>>>(bond_emb);
    split_kernel<<<(WN4 + 255) / 256, 256>>>(W1, p_w1h, p_w1l, WN4);
    split_kernel<<<(WN4 + 255) / 256, 256>>>(W2, p_w2h, p_w2l, WN4);
    hist_zero_kernel<<<(N_NODES + 255) / 256, 256>>>();
    hist_kernel<<<EB, 256>>>(edge_index);
    scan_kernel<<<1, 1024>>>();
    scatter_kernel<<<EB, 256>>>(edge_index, edge_attr, edge_weight);

    for (int l = 0; l < NLAYERS; l++) {
        const float* src_feat = (l == 0) ? p_h : p_z;
        const float* st_prev  = p_st2 + (size_t)(l > 0 ? l - 1 : 0) * 2 * D;
        const float* bng_prev = bn_g + (size_t)(l > 0 ? l - 1 : 0) * D;
        const float* bnb_prev = bn_b + (size_t)(l > 0 ? l - 1 : 0) * D;
        agg_kernel<<<(N_NODES * 32 + 255) / 256, 256>>>(
            src_feat, eps_p, l, l > 0 ? 1 : 0, st_prev, bng_prev, bnb_prev);

        gemm_presplit_kernel<D, D2><<<dim3(D2 / GBN, MB), 256, SMEM_GEMM>>>(
            p_zh, p_zl, p_w1h + (size_t)l * D * D2, p_w1l + (size_t)l * D * D2,
            b1 + (size_t)l * D2, p_y1, p_st1 + (size_t)l * 2 * D2);

        gemm_fused_kernel<D2, D><<<dim3(D / GBN, MB), 256, SMEM_GEMM>>>(
            p_y1, p_w2h + (size_t)l * D2 * D, p_w2l + (size_t)l * D2 * D,
            b2 + (size_t)l * D, p_z, p_st1 + (size_t)l * 2 * D2,
            bn1_g + (size_t)l * D2, bn1_b + (size_t)l * D2,
            p_st2 + (size_t)l * 2 * D);
    }
    bn_apply_kernel<<<ELT_BLOCKS, 256>>>(out, p_st2 + (size_t)(NLAYERS - 1) * 2 * D,
                                         bn_g + (size_t)(NLAYERS - 1) * D,
                                         bn_b + (size_t)(NLAYERS - 1) * D);
    (void)in_sizes; (void)n_in; (void)out_size;
}

// round 15
// speedup vs baseline: 1.0093x; 1.0093x over previous
#include <cuda_runtime.h>
#include <cuda_bf16.h>
#include <cstdint>

#define N_NODES 50000
#define N_EDGES 600000
#define D 128
#define D2 256
#define NLAYERS 5

// ---------------- scratch (static device memory; no allocations) -------------
__device__ float g_h[N_NODES * D];
__device__ float g_z[N_NODES * D];                // GEMM2 output (y2)
__device__ float g_y1[N_NODES * D2];
__device__ __nv_bfloat16 g_zh[N_NODES * D], g_zl[N_NODES * D];   // agg output, pre-split
__device__ float g_bond_tab[NLAYERS * 512 * D];
__device__ int   g_deg[N_NODES];
__device__ int   g_rowptr[N_NODES + 1];
__device__ int   g_woff[N_NODES];
__device__ uint2 g_edge[N_EDGES];                 // {src | combo<<17, w}
__device__ __nv_bfloat16 g_w1h[NLAYERS * D * D2], g_w1l[NLAYERS * D * D2];
__device__ __nv_bfloat16 g_w2h[NLAYERS * D2 * D], g_w2l[NLAYERS * D2 * D];
__device__ float g_stats1[2 * D2];
__device__ float g_stats2[2 * D];

// ---------------- helpers ----------------------------------------------------
__device__ __forceinline__ uint32_t smem_u32(const void* p) {
    return (uint32_t)__cvta_generic_to_shared(p);
}
__device__ __forceinline__ void ldsm4(uint32_t addr, uint32_t& r0, uint32_t& r1,
                                      uint32_t& r2, uint32_t& r3) {
    asm volatile("ldmatrix.sync.aligned.m8n8.x4.shared.b16 {%0,%1,%2,%3}, [%4];"
                 : "=r"(r0), "=r"(r1), "=r"(r2), "=r"(r3) : "r"(addr));
}
__device__ __forceinline__ void ldsm4t(uint32_t addr, uint32_t& r0, uint32_t& r1,
                                       uint32_t& r2, uint32_t& r3) {
    asm volatile("ldmatrix.sync.aligned.m8n8.x4.trans.shared.b16 {%0,%1,%2,%3}, [%4];"
                 : "=r"(r0), "=r"(r1), "=r"(r2), "=r"(r3) : "r"(addr));
}
__device__ __forceinline__ void mma16816(float* c, const uint32_t* a, const uint32_t* b) {
    asm volatile(
        "mma.sync.aligned.m16n8k16.row.col.f32.bf16.bf16.f32 "
        "{%0,%1,%2,%3}, {%4,%5,%6,%7}, {%8,%9}, {%0,%1,%2,%3};"
        : "+f"(c[0]), "+f"(c[1]), "+f"(c[2]), "+f"(c[3])
        : "r"(a[0]), "r"(a[1]), "r"(a[2]), "r"(a[3]), "r"(b[0]), "r"(b[1]));
}
__device__ __forceinline__ void cp_async16(uint32_t dst, const void* src, int szbytes) {
    asm volatile("cp.async.cg.shared.global [%0], [%1], 16, %2;"
                 :: "r"(dst), "l"(src), "r"(szbytes));
}
__device__ __forceinline__ void cp_commit() { asm volatile("cp.async.commit_group;"); }
__device__ __forceinline__ void cp_wait0() { asm volatile("cp.async.wait_group 0;"); }
__device__ __forceinline__ void cp_wait1() { asm volatile("cp.async.wait_group 1;"); }
__device__ __forceinline__ void split2(float x0, float x1,
                                       __nv_bfloat162& hi, __nv_bfloat162& lo) {
    __nv_bfloat16 h0 = __float2bfloat16_rn(x0);
    __nv_bfloat16 h1 = __float2bfloat16_rn(x1);
    hi = __nv_bfloat162(h0, h1);
    lo = __nv_bfloat162(__float2bfloat16_rn(x0 - __bfloat162float(h0)),
                        __float2bfloat16_rn(x1 - __bfloat162float(h1)));
}

// ---------------- node embedding + stats zero + deg zero ----------------------
__global__ void embed_kernel(const int* __restrict__ x,
                             const float* __restrict__ atom_emb) {
    int idx = blockIdx.x * blockDim.x + threadIdx.x;
    if (idx < 2 * D2) g_stats1[idx] = 0.f;
    if (idx < 2 * D)  g_stats2[idx] = 0.f;
    if (idx < N_NODES) g_deg[idx] = 0;            // fused hist_zero
    int node = idx >> 5, lane = idx & 31;
    if (node >= N_NODES) return;
    const int* xr = x + node * 9;
    float4 acc = make_float4(0.f, 0.f, 0.f, 0.f);
#pragma unroll
    for (int f = 0; f < 9; f++) {
        int v = __ldg(xr + f);
        float4 t = ((const float4*)(atom_emb + (size_t)(f * 64 + v) * D))[lane];
        acc.x += t.x; acc.y += t.y; acc.z += t.z; acc.w += t.w;
    }
    ((float4*)(g_h + (size_t)node * D))[lane] = acc;
}

// ---------------- combined bond table ----------------------------------------
__global__ void bond_table_kernel(const float* __restrict__ bond_emb) {
    int wid = (blockIdx.x * blockDim.x + threadIdx.x) >> 5;
    int lane = threadIdx.x & 31;
    if (wid >= NLAYERS * 512) return;
    int l = wid >> 9, combo = wid & 511;
    int a0 = combo & 7, a1 = (combo >> 3) & 7, a2 = combo >> 6;
    const float* be = bond_emb + (size_t)l * 3 * 8 * D;
    float4 v0 = ((const float4*)(be + a0 * D))[lane];
    float4 v1 = ((const float4*)(be + (8 + a1) * D))[lane];
    float4 v2 = ((const float4*)(be + (16 + a2) * D))[lane];
    float4 s;
    s.x = v0.x + v1.x + v2.x;
    s.y = v0.y + v1.y + v2.y;
    s.z = v0.z + v1.z + v2.z;
    s.w = v0.w + v1.w + v2.w;
    ((float4*)(g_bond_tab + (size_t)wid * D))[lane] = s;
}

// ---------------- CSR build ---------------------------------------------------
__global__ void hist_kernel(const int* __restrict__ edge_index) {
    int e = blockIdx.x * blockDim.x + threadIdx.x;
    if (e >= N_EDGES) return;
    atomicAdd(&g_deg[__ldg(edge_index + N_EDGES + e)], 1);
}
__global__ void scan_kernel() {
    __shared__ int part[1024];
    const int CH = (N_NODES + 1023) / 1024;
    int t = threadIdx.x;
    int base = t * CH;
    int hi = min(base + CH, N_NODES);
    int s = 0;
    for (int i = base; i < hi; i++) s += g_deg[i];
    part[t] = s;
    __syncthreads();
    for (int off = 1; off < 1024; off <<= 1) {
        int v = (t >= off) ? part[t - off] : 0;
        __syncthreads();
        part[t] += v;
        __syncthreads();
    }
    int run = (t > 0) ? part[t - 1] : 0;
    for (int i = base; i < hi; i++) {
        g_rowptr[i] = run;
        g_woff[i] = run;
        run += g_deg[i];
    }
    if (t == 1023) g_rowptr[N_NODES] = part[1023];
}
__global__ void scatter_kernel(const int* __restrict__ edge_index,
                               const int* __restrict__ edge_attr,
                               const float* __restrict__ edge_weight) {
    int e = blockIdx.x * blockDim.x + threadIdx.x;
    if (e >= N_EDGES) return;
    int s = __ldg(edge_index + e);
    int d = __ldg(edge_index + N_EDGES + e);
    int a0 = __ldg(edge_attr + e * 3 + 0);
    int a1 = __ldg(edge_attr + e * 3 + 1);
    int a2 = __ldg(edge_attr + e * 3 + 2);
    uint32_t combo = (uint32_t)(a0 + (a1 << 3) + (a2 << 6));
    int pos = atomicAdd(&g_woff[d], 1);
    g_edge[pos] = make_uint2((uint32_t)s | (combo << 17),
                             __float_as_uint(__ldg(edge_weight + e)));
}

// ---- CSR aggregation -> writes PRE-SPLIT bf16 hi/lo z; re-zeroes stats ------
// Edge-record prefetch: next record's L2 latency overlaps current gathers.
__global__ void agg_kernel(const float* __restrict__ eps_p, int l) {
    int t = blockIdx.x * blockDim.x + threadIdx.x;
    if (t < 2 * D2) g_stats1[t] = 0.f;
    if (t < 2 * D)  g_stats2[t] = 0.f;
    int gw = t >> 5;
    int lane = threadIdx.x & 31;
    if (gw >= N_NODES) return;
    const float* tab = g_bond_tab + (size_t)l * 512 * D;
    float s = 1.f + __ldg(eps_p + l);
    float4 acc = ((const float4*)(g_h + (size_t)gw * D))[lane];
    acc.x *= s; acc.y *= s; acc.z *= s; acc.w *= s;
    int beg = __ldg(&g_rowptr[gw]);
    int end = __ldg(&g_rowptr[gw + 1]);
    uint2 md = (beg < end) ? __ldg(&g_edge[beg]) : make_uint2(0u, 0u);
    for (int e = beg; e < end; e++) {
        uint2 cur = md;
        if (e + 1 < end) md = __ldg(&g_edge[e + 1]);   // prefetch next record
        int src = cur.x & 0x1FFFF;
        int combo = cur.x >> 17;
        float w = __uint_as_float(cur.y);
        float4 hv = __ldg(((const float4*)(g_h + (size_t)src * D)) + lane);
        float4 ev = __ldg(((const float4*)(tab + (size_t)combo * D)) + lane);
        acc.x += fmaxf(hv.x + ev.x, 0.f) * w;
        acc.y += fmaxf(hv.y + ev.y, 0.f) * w;
        acc.z += fmaxf(hv.z + ev.z, 0.f) * w;
        acc.w += fmaxf(hv.w + ev.w, 0.f) * w;
    }
    __nv_bfloat162 h0, l0, h1, l1;
    split2(acc.x, acc.y, h0, l0);
    split2(acc.z, acc.w, h1, l1);
    __nv_bfloat162* zh = (__nv_bfloat162*)(g_zh + (size_t)gw * D);
    __nv_bfloat162* zl = (__nv_bfloat162*)(g_zl + (size_t)gw * D);
    zh[lane * 2] = h0; zh[lane * 2 + 1] = h1;
    zl[lane * 2] = l0; zl[lane * 2 + 1] = l1;
}

// ---------------- fp32 -> bf16 hi/lo split (weights preprocess only) ---------
__global__ void split_kernel(const float* __restrict__ src,
                             __nv_bfloat16* __restrict__ dh,
                             __nv_bfloat16* __restrict__ dl, int n4) {
    int i = blockIdx.x * blockDim.x + threadIdx.x;
    if (i >= n4) return;
    float4 v = ((const float4*)src)[i];
    __nv_bfloat162 h0, l0, h1, l1;
    split2(v.x, v.y, h0, l0);
    split2(v.z, v.w, h1, l1);
    ((__nv_bfloat162*)dh)[i * 2]     = h0;
    ((__nv_bfloat162*)dh)[i * 2 + 1] = h1;
    ((__nv_bfloat162*)dl)[i * 2]     = l0;
    ((__nv_bfloat162*)dl)[i * 2 + 1] = l1;
}

// ---------------- common tile geometry ---------------------------------------
#define A_STRIDE 40
#define B_STRIDE 136
#define GBM 128
#define GBN 128
#define GBK 32
#define A_BYTES (GBM * A_STRIDE * 2)
#define B_BYTES (GBK * B_STRIDE * 2)
#define STAGE_BYTES (2 * A_BYTES + 2 * B_BYTES)
#define SMEM_GEMM (2 * STAGE_BYTES)

// ======== GEMM variant 1: all-presplit inputs (A and B bf16 hi/lo, cp.async) =
template <int K, int NOUT>
__global__ __launch_bounds__(256, 2)
void gemm_presplit_kernel(const __nv_bfloat16* __restrict__ Ah_g,
                          const __nv_bfloat16* __restrict__ Al_g,
                          const __nv_bfloat16* __restrict__ Bh_g,
                          const __nv_bfloat16* __restrict__ Bl_g,
                          const float* __restrict__ bias, float* __restrict__ C,
                          float* __restrict__ stats) {
    const int NT = K / GBK;
    extern __shared__ __align__(16) char smem[];
    __shared__ float ssum[GBN], ssq[GBN];

    int tid = threadIdx.x;
    int lane = tid & 31, warp = tid >> 5;
    int wm = warp & 1, wn = warp >> 1;
    int rowBase = blockIdx.y * GBM;
    int colBase = blockIdx.x * GBN;

    if (tid < GBN) { ssum[tid] = 0.f; ssq[tid] = 0.f; }

    float acc[4][4][4];
#pragma unroll
    for (int i = 0; i < 4; i++)
#pragma unroll
        for (int j = 0; j < 4; j++)
#pragma unroll
            for (int q = 0; q < 4; q++) acc[i][j][q] = 0.f;

    auto pA_h = [&](int s) { return (__nv_bfloat16*)(smem + s * STAGE_BYTES); };
    auto pA_l = [&](int s) { return (__nv_bfloat16*)(smem + s * STAGE_BYTES + A_BYTES); };
    auto pB_h = [&](int s) { return (__nv_bfloat16*)(smem + s * STAGE_BYTES + 2 * A_BYTES); };
    auto pB_l = [&](int s) { return (__nv_bfloat16*)(smem + s * STAGE_BYTES + 2 * A_BYTES + B_BYTES); };

    auto LOADS = [&](int kt, int s) {
#pragma unroll
        for (int i = 0; i < 2; i++) {
            int id = tid + i * 256;
            int r = id >> 2, c = (id & 3) * 8;
            int grow = rowBase + r;
            int sz = (grow < N_NODES) ? 16 : 0;
            cp_async16(smem_u32(pA_h(s) + r * A_STRIDE + c),
                       Ah_g + (size_t)grow * K + kt + c, sz);
            cp_async16(smem_u32(pA_l(s) + r * A_STRIDE + c),
                       Al_g + (size_t)grow * K + kt + c, sz);
        }
#pragma unroll
        for (int i = 0; i < 2; i++) {
            int id = tid + i * 256;
            int r = id >> 4, c = (id & 15) * 8;
            cp_async16(smem_u32(pB_h(s) + r * B_STRIDE + c),
                       Bh_g + (size_t)(kt + r) * NOUT + colBase + c, 16);
            cp_async16(smem_u32(pB_l(s) + r * B_STRIDE + c),
                       Bl_g + (size_t)(kt + r) * NOUT + colBase + c, 16);
        }
    };

    int lr = lane & 15;
    int lc = (lane >> 4) << 3;

    LOADS(0, 0);
    cp_commit();

#pragma unroll 1
    for (int t = 0; t < NT; t++) {
        int s = t & 1;
        if (t + 1 < NT) {
            LOADS((t + 1) * GBK, s ^ 1);
            cp_commit();
            cp_wait1();
        } else {
            cp_wait0();
        }
        __syncthreads();

        const __nv_bfloat16* Ahs = pA_h(s);
        const __nv_bfloat16* Als = pA_l(s);
        const __nv_bfloat16* Bhs = pB_h(s);
        const __nv_bfloat16* Bls = pB_l(s);
#pragma unroll
        for (int ks = 0; ks < GBK; ks += 16) {
            uint32_t bh[4][2], bl[4][2];
#pragma unroll
            for (int nb = 0; nb < 2; nb++) {
                int ncol = wn * 32 + nb * 16 + lc;
                uint32_t r0, r1, r2, r3;
                ldsm4t(smem_u32(Bhs + (ks + lr) * B_STRIDE + ncol), r0, r1, r2, r3);
                bh[nb * 2][0] = r0; bh[nb * 2][1] = r1;
                bh[nb * 2 + 1][0] = r2; bh[nb * 2 + 1][1] = r3;
                ldsm4t(smem_u32(Bls + (ks + lr) * B_STRIDE + ncol), r0, r1, r2, r3);
                bl[nb * 2][0] = r0; bl[nb * 2][1] = r1;
                bl[nb * 2 + 1][0] = r2; bl[nb * 2 + 1][1] = r3;
            }
#pragma unroll
            for (int mf = 0; mf < 4; mf++) {
                int mrow = wm * 64 + mf * 16 + lr;
                uint32_t ah[4], al[4];
                ldsm4(smem_u32(Ahs + mrow * A_STRIDE + ks + lc), ah[0], ah[1], ah[2], ah[3]);
                ldsm4(smem_u32(Als + mrow * A_STRIDE + ks + lc), al[0], al[1], al[2], al[3]);
#pragma unroll
                for (int nf = 0; nf < 4; nf++) {
                    mma16816(acc[mf][nf], ah, bh[nf]);
                    mma16816(acc[mf][nf], ah, bl[nf]);
                    mma16816(acc[mf][nf], al, bh[nf]);
                }
            }
        }
        __syncthreads();
    }

    int crow = lane >> 2;
    int ccol = (lane & 3) * 2;
    float bcol8[4][2];
#pragma unroll
    for (int nf = 0; nf < 4; nf++) {
        bcol8[nf][0] = bias[colBase + wn * 32 + nf * 8 + ccol];
        bcol8[nf][1] = bias[colBase + wn * 32 + nf * 8 + ccol + 1];
    }
    float psum[4][2] = {}, psq[4][2] = {};
#pragma unroll
    for (int mf = 0; mf < 4; mf++)
#pragma unroll
        for (int r2 = 0; r2 < 2; r2++) {
            int r = rowBase + wm * 64 + mf * 16 + crow + r2 * 8;
            if (r < N_NODES) {
#pragma unroll
                for (int nf = 0; nf < 4; nf++) {
                    float v0 = acc[mf][nf][r2 * 2 + 0] + bcol8[nf][0];
                    float v1 = acc[mf][nf][r2 * 2 + 1] + bcol8[nf][1];
                    *(float2*)(C + (size_t)r * NOUT + colBase + wn * 32 + nf * 8 + ccol) =
                        make_float2(v0, v1);
                    psum[nf][0] += v0; psq[nf][0] += v0 * v0;
                    psum[nf][1] += v1; psq[nf][1] += v1 * v1;
                }
            }
        }
    __syncthreads();
#pragma unroll
    for (int nf = 0; nf < 4; nf++) {
        int c = wn * 32 + nf * 8 + ccol;
        atomicAdd(&ssum[c],     psum[nf][0]);
        atomicAdd(&ssum[c + 1], psum[nf][1]);
        atomicAdd(&ssq[c],      psq[nf][0]);
        atomicAdd(&ssq[c + 1],  psq[nf][1]);
    }
    __syncthreads();
    if (tid < GBN) {
        atomicAdd(&stats[colBase + tid], ssum[tid]);
        atomicAdd(&stats[NOUT + colBase + tid], ssq[tid]);
    }
}

// ======== GEMM variant 2: fused BN1+relu+split on fp32 A (GEMM2) =============
template <int K, int NOUT>
__global__ __launch_bounds__(256, 2)
void gemm_fused_kernel(const float* __restrict__ A,
                       const __nv_bfloat16* __restrict__ Bh_g,
                       const __nv_bfloat16* __restrict__ Bl_g,
                       const float* __restrict__ bias, float* __restrict__ C,
                       const float* __restrict__ stats_in,
                       const float* __restrict__ bng, const float* __restrict__ bnb,
                       float* __restrict__ stats) {
    const int NT = K / GBK;
    extern __shared__ __align__(16) char smem[];
    __shared__ float ssum[GBN], ssq[GBN];
    __shared__ __align__(16) float s_sc[K], s_sh[K];

    int tid = threadIdx.x;
    int lane = tid & 31, warp = tid >> 5;
    int wm = warp & 1, wn = warp >> 1;
    int rowBase = blockIdx.y * GBM;
    int colBase = blockIdx.x * GBN;

    if (tid < GBN) { ssum[tid] = 0.f; ssq[tid] = 0.f; }

    if (tid < K) {
        const float invn = 1.f / (float)N_NODES;
        float m = stats_in[tid] * invn;
        float var = stats_in[K + tid] * invn - m * m;
        float sc = bng[tid] * rsqrtf(var + 1e-5f);
        s_sc[tid] = sc;
        s_sh[tid] = bnb[tid] - m * sc;
    }
    __syncthreads();

    float acc[4][4][4];
#pragma unroll
    for (int i = 0; i < 4; i++)
#pragma unroll
        for (int j = 0; j < 4; j++)
#pragma unroll
            for (int q = 0; q < 4; q++) acc[i][j][q] = 0.f;

    auto pA_h = [&](int s) { return (__nv_bfloat16*)(smem + s * STAGE_BYTES); };
    auto pA_l = [&](int s) { return (__nv_bfloat16*)(smem + s * STAGE_BYTES + A_BYTES); };
    auto pB_h = [&](int s) { return (__nv_bfloat16*)(smem + s * STAGE_BYTES + 2 * A_BYTES); };
    auto pB_l = [&](int s) { return (__nv_bfloat16*)(smem + s * STAGE_BYTES + 2 * A_BYTES + B_BYTES); };

    int ar  = tid >> 1;
    int acb = (tid & 1) * 16;
    int agrow = rowBase + ar;
    bool arow_ok = (agrow < N_NODES);

    float4 areg[4];

    auto LOAD_A = [&](int kt) {
        if (arow_ok) {
            const float* ap = A + (size_t)agrow * K + kt + acb;
            areg[0] = *(const float4*)(ap + 0);
            areg[1] = *(const float4*)(ap + 4);
            areg[2] = *(const float4*)(ap + 8);
            areg[3] = *(const float4*)(ap + 12);
#pragma unroll
            for (int j = 0; j < 4; j++) {
                float4 sc = *(const float4*)(s_sc + kt + acb + j * 4);
                float4 sh = *(const float4*)(s_sh + kt + acb + j * 4);
                areg[j].x = fmaxf(fmaf(areg[j].x, sc.x, sh.x), 0.f);
                areg[j].y = fmaxf(fmaf(areg[j].y, sc.y, sh.y), 0.f);
                areg[j].z = fmaxf(fmaf(areg[j].z, sc.z, sh.z), 0.f);
                areg[j].w = fmaxf(fmaf(areg[j].w, sc.w, sh.w), 0.f);
            }
        } else {
            float4 z4 = make_float4(0.f, 0.f, 0.f, 0.f);
            areg[0] = z4; areg[1] = z4; areg[2] = z4; areg[3] = z4;
        }
    };
    auto STORE_A = [&](int s) {
        __nv_bfloat16* dh = pA_h(s) + ar * A_STRIDE + acb;
        __nv_bfloat16* dl = pA_l(s) + ar * A_STRIDE + acb;
#pragma unroll
        for (int j = 0; j < 4; j++) {
            __nv_bfloat162 h0, l0, h1, l1;
            split2(areg[j].x, areg[j].y, h0, l0);
            split2(areg[j].z, areg[j].w, h1, l1);
            *(__nv_bfloat162*)(dh + j * 4)     = h0;
            *(__nv_bfloat162*)(dh + j * 4 + 2) = h1;
            *(__nv_bfloat162*)(dl + j * 4)     = l0;
            *(__nv_bfloat162*)(dl + j * 4 + 2) = l1;
        }
    };
    auto LOAD_B = [&](int kt, int s) {
#pragma unroll
        for (int i = 0; i < 2; i++) {
            int id = tid + i * 256;
            int r = id >> 4, c = (id & 15) * 8;
            cp_async16(smem_u32(pB_h(s) + r * B_STRIDE + c),
                       Bh_g + (size_t)(kt + r) * NOUT + colBase + c, 16);
            cp_async16(smem_u32(pB_l(s) + r * B_STRIDE + c),
                       Bl_g + (size_t)(kt + r) * NOUT + colBase + c, 16);
        }
    };

    int lr = lane & 15;
    int lc = (lane >> 4) << 3;

    LOAD_B(0, 0); cp_commit();
    LOAD_A(0);
    STORE_A(0);
    cp_wait0();
    __syncthreads();

    int buf = 0;
#pragma unroll 1
    for (int t = 0; t < NT; t++) {
        if (t + 1 < NT) {
            LOAD_B((t + 1) * GBK, buf ^ 1);
            cp_commit();
            LOAD_A((t + 1) * GBK);
        }

        const __nv_bfloat16* Ahs = pA_h(buf);
        const __nv_bfloat16* Als = pA_l(buf);
        const __nv_bfloat16* Bhs = pB_h(buf);
        const __nv_bfloat16* Bls = pB_l(buf);
#pragma unroll
        for (int ks = 0; ks < GBK; ks += 16) {
            uint32_t bh[4][2], bl[4][2];
#pragma unroll
            for (int nb = 0; nb < 2; nb++) {
                int ncol = wn * 32 + nb * 16 + lc;
                uint32_t r0, r1, r2, r3;
                ldsm4t(smem_u32(Bhs + (ks + lr) * B_STRIDE + ncol), r0, r1, r2, r3);
                bh[nb * 2][0] = r0; bh[nb * 2][1] = r1;
                bh[nb * 2 + 1][0] = r2; bh[nb * 2 + 1][1] = r3;
                ldsm4t(smem_u32(Bls + (ks + lr) * B_STRIDE + ncol), r0, r1, r2, r3);
                bl[nb * 2][0] = r0; bl[nb * 2][1] = r1;
                bl[nb * 2 + 1][0] = r2; bl[nb * 2 + 1][1] = r3;
            }
#pragma unroll
            for (int mf = 0; mf < 4; mf++) {
                int mrow = wm * 64 + mf * 16 + lr;
                uint32_t ah[4], al[4];
                ldsm4(smem_u32(Ahs + mrow * A_STRIDE + ks + lc), ah[0], ah[1], ah[2], ah[3]);
                ldsm4(smem_u32(Als + mrow * A_STRIDE + ks + lc), al[0], al[1], al[2], al[3]);
#pragma unroll
                for (int nf = 0; nf < 4; nf++) {
                    mma16816(acc[mf][nf], ah, bh[nf]);
                    mma16816(acc[mf][nf], ah, bl[nf]);
                    mma16816(acc[mf][nf], al, bh[nf]);
                }
            }
        }

        if (t + 1 < NT) {
            STORE_A(buf ^ 1);
            cp_wait0();
            __syncthreads();
            buf ^= 1;
        }
    }

    int crow = lane >> 2;
    int ccol = (lane & 3) * 2;
    float bcol8[4][2];
#pragma unroll
    for (int nf = 0; nf < 4; nf++) {
        bcol8[nf][0] = bias[colBase + wn * 32 + nf * 8 + ccol];
        bcol8[nf][1] = bias[colBase + wn * 32 + nf * 8 + ccol + 1];
    }
    float psum[4][2] = {}, psq[4][2] = {};
#pragma unroll
    for (int mf = 0; mf < 4; mf++)
#pragma unroll
        for (int r2 = 0; r2 < 2; r2++) {
            int r = rowBase + wm * 64 + mf * 16 + crow + r2 * 8;
            if (r < N_NODES) {
#pragma unroll
                for (int nf = 0; nf < 4; nf++) {
                    float v0 = acc[mf][nf][r2 * 2 + 0] + bcol8[nf][0];
                    float v1 = acc[mf][nf][r2 * 2 + 1] + bcol8[nf][1];
                    *(float2*)(C + (size_t)r * NOUT + colBase + wn * 32 + nf * 8 + ccol) =
                        make_float2(v0, v1);
                    psum[nf][0] += v0; psq[nf][0] += v0 * v0;
                    psum[nf][1] += v1; psq[nf][1] += v1 * v1;
                }
            }
        }
    __syncthreads();
#pragma unroll
    for (int nf = 0; nf < 4; nf++) {
        int c = wn * 32 + nf * 8 + ccol;
        atomicAdd(&ssum[c],     psum[nf][0]);
        atomicAdd(&ssum[c + 1], psum[nf][1]);
        atomicAdd(&ssq[c],      psq[nf][0]);
        atomicAdd(&ssq[c + 1],  psq[nf][1]);
    }
    __syncthreads();
    if (tid < GBN) {
        atomicAdd(&stats[colBase + tid], ssum[tid]);
        atomicAdd(&stats[NOUT + colBase + tid], ssq[tid]);
    }
}

// ------- apply BN2 (fused finalize in prologue); write h or final out --------
__global__ void bn_apply_kernel(float* __restrict__ final_out,
                                const float* __restrict__ bng,
                                const float* __restrict__ bnb, int l) {
    __shared__ __align__(16) float s_sc[D], s_sh[D];
    int tid = threadIdx.x;
    if (tid < D) {
        const float invn = 1.f / (float)N_NODES;
        float m = g_stats2[tid] * invn;
        float var = g_stats2[D + tid] * invn - m * m;
        float sc = bng[tid] * rsqrtf(var + 1e-5f);
        s_sc[tid] = sc;
        s_sh[tid] = bnb[tid] - m * sc;
    }
    __syncthreads();
    int idx = blockIdx.x * blockDim.x + tid;
    if (idx >= N_NODES * (D / 4)) return;
    int c4 = idx & 31;
    float4 v = ((const float4*)g_z)[idx];
    float4 sc = ((const float4*)s_sc)[c4];
    float4 sh = ((const float4*)s_sh)[c4];
    v.x = fmaf(v.x, sc.x, sh.x);
    v.y = fmaf(v.y, sc.y, sh.y);
    v.z = fmaf(v.z, sc.z, sh.z);
    v.w = fmaf(v.w, sc.w, sh.w);
    if (l < NLAYERS - 1) {
        v.x = fmaxf(v.x, 0.f); v.y = fmaxf(v.y, 0.f);
        v.z = fmaxf(v.z, 0.f); v.w = fmaxf(v.w, 0.f);
        ((float4*)g_h)[idx] = v;
    } else {
        ((float4*)final_out)[idx] = v;
    }
}

// ---------------- launcher ---------------------------------------------------
extern "C" void kernel_launch(void* const* d_in, const int* in_sizes, int n_in,
                              void* d_out, int out_size) {
    const int*   x           = (const int*)d_in[0];
    const int*   edge_index  = (const int*)d_in[1];
    const int*   edge_attr   = (const int*)d_in[2];
    const float* edge_weight = (const float*)d_in[3];
    const float* atom_emb    = (const float*)d_in[4];
    const float* bond_emb    = (const float*)d_in[5];
    const float* W1          = (const float*)d_in[6];
    const float* b1          = (const float*)d_in[7];
    const float* bn1_g       = (const float*)d_in[8];
    const float* bn1_b       = (const float*)d_in[9];
    const float* W2          = (const float*)d_in[10];
    const float* b2          = (const float*)d_in[11];
    const float* eps_p       = (const float*)d_in[12];
    const float* bn_g        = (const float*)d_in[13];
    const float* bn_b        = (const float*)d_in[14];
    float* out = (float*)d_out;

    float *p_z, *p_y1, *p_st1, *p_st2;
    __nv_bfloat16 *p_zh, *p_zl, *p_w1h, *p_w1l, *p_w2h, *p_w2l;
    cudaGetSymbolAddress((void**)&p_z,   g_z);
    cudaGetSymbolAddress((void**)&p_y1,  g_y1);
    cudaGetSymbolAddress((void**)&p_st1, g_stats1);
    cudaGetSymbolAddress((void**)&p_st2, g_stats2);
    cudaGetSymbolAddress((void**)&p_zh,  g_zh);
    cudaGetSymbolAddress((void**)&p_zl,  g_zl);
    cudaGetSymbolAddress((void**)&p_w1h, g_w1h);
    cudaGetSymbolAddress((void**)&p_w1l, g_w1l);
    cudaGetSymbolAddress((void**)&p_w2h, g_w2h);
    cudaGetSymbolAddress((void**)&p_w2l, g_w2l);

    cudaFuncSetAttribute(gemm_presplit_kernel<D, D2>,
                         cudaFuncAttributeMaxDynamicSharedMemorySize, SMEM_GEMM);
    cudaFuncSetAttribute(gemm_fused_kernel<D2, D>,
                         cudaFuncAttributeMaxDynamicSharedMemorySize, SMEM_GEMM);

    const int ELT_BLOCKS = (N_NODES * (D / 4) + 255) / 256;
    const int MB = (N_NODES + GBM - 1) / GBM;
    const int WN4 = NLAYERS * D * D2 / 4;
    const int EB = (N_EDGES + 255) / 256;

    embed_kernel<<<(N_NODES * 32 + 255) / 256, 256>>>(x, atom_emb);
    bond_table_kernel<<<(NLAYERS * 512 * 32 + 255) / 256, 256>>>(bond_emb);
    split_kernel<<<(WN4 + 255) / 256, 256>>>(W1, p_w1h, p_w1l, WN4);
    split_kernel<<<(WN4 + 255) / 256, 256>>>(W2, p_w2h, p_w2l, WN4);
    hist_kernel<<<EB, 256>>>(edge_index);
    scan_kernel<<<1, 1024>>>();
    scatter_kernel<<<EB, 256>>>(edge_index, edge_attr, edge_weight);

    for (int l = 0; l < NLAYERS; l++) {
        agg_kernel<<<(N_NODES * 32 + 255) / 256, 256>>>(eps_p, l);

        gemm_presplit_kernel<D, D2><<<dim3(D2 / GBN, MB), 256, SMEM_GEMM>>>(
            p_zh, p_zl, p_w1h + (size_t)l * D * D2, p_w1l + (size_t)l * D * D2,
            b1 + (size_t)l * D2, p_y1, p_st1);

        gemm_fused_kernel<D2, D><<<dim3(D / GBN, MB), 256, SMEM_GEMM>>>(
            p_y1, p_w2h + (size_t)l * D2 * D, p_w2l + (size_t)l * D2 * D,
            b2 + (size_t)l * D, p_z, p_st1,
            bn1_g + (size_t)l * D2, bn1_b + (size_t)l * D2, p_st2);

        bn_apply_kernel<<<ELT_BLOCKS, 256>>>(out, bn_g + (size_t)l * D,
                                             bn_b + (size_t)l * D, l);
    }
    (void)in_sizes; (void)n_in; (void)out_size;
}

// round 16
// speedup vs baseline: 1.0281x; 1.0186x over previous
#include <cuda_runtime.h>
#include <cuda_bf16.h>
#include <cstdint>

#define N_NODES 50000
#define N_EDGES 600000
#define D 128
#define D2 256
#define NLAYERS 5

// ---------------- scratch (static device memory; no allocations) -------------
__device__ float g_h[N_NODES * D];
__device__ float g_z[N_NODES * D];                // GEMM2 output (y2)
__device__ float g_y1[N_NODES * D2];
__device__ __nv_bfloat16 g_zh[N_NODES * D], g_zl[N_NODES * D];   // agg output, pre-split
__device__ float g_bond_tab[NLAYERS * 512 * D];
__device__ int   g_deg[N_NODES];
__device__ int   g_rowptr[N_NODES + 1];
__device__ int   g_woff[N_NODES];
__device__ uint2 g_edge[N_EDGES];                 // {src | combo<<17, w}
__device__ __nv_bfloat16 g_w1h[NLAYERS * D * D2], g_w1l[NLAYERS * D * D2];
__device__ __nv_bfloat16 g_w2h[NLAYERS * D2 * D], g_w2l[NLAYERS * D2 * D];
__device__ float g_stats1[2 * D2];
__device__ float g_stats2[2 * D];

// ---------------- helpers ----------------------------------------------------
__device__ __forceinline__ uint32_t smem_u32(const void* p) {
    return (uint32_t)__cvta_generic_to_shared(p);
}
__device__ __forceinline__ void ldsm4(uint32_t addr, uint32_t& r0, uint32_t& r1,
                                      uint32_t& r2, uint32_t& r3) {
    asm volatile("ldmatrix.sync.aligned.m8n8.x4.shared.b16 {%0,%1,%2,%3}, [%4];"
                 : "=r"(r0), "=r"(r1), "=r"(r2), "=r"(r3) : "r"(addr));
}
__device__ __forceinline__ void ldsm4t(uint32_t addr, uint32_t& r0, uint32_t& r1,
                                       uint32_t& r2, uint32_t& r3) {
    asm volatile("ldmatrix.sync.aligned.m8n8.x4.trans.shared.b16 {%0,%1,%2,%3}, [%4];"
                 : "=r"(r0), "=r"(r1), "=r"(r2), "=r"(r3) : "r"(addr));
}
__device__ __forceinline__ void mma16816(float* c, const uint32_t* a, const uint32_t* b) {
    asm volatile(
        "mma.sync.aligned.m16n8k16.row.col.f32.bf16.bf16.f32 "
        "{%0,%1,%2,%3}, {%4,%5,%6,%7}, {%8,%9}, {%0,%1,%2,%3};"
        : "+f"(c[0]), "+f"(c[1]), "+f"(c[2]), "+f"(c[3])
        : "r"(a[0]), "r"(a[1]), "r"(a[2]), "r"(a[3]), "r"(b[0]), "r"(b[1]));
}
__device__ __forceinline__ void cp_async16(uint32_t dst, const void* src, int szbytes) {
    asm volatile("cp.async.cg.shared.global [%0], [%1], 16, %2;"
                 :: "r"(dst), "l"(src), "r"(szbytes));
}
__device__ __forceinline__ void cp_commit() { asm volatile("cp.async.commit_group;"); }
__device__ __forceinline__ void cp_wait0() { asm volatile("cp.async.wait_group 0;"); }
__device__ __forceinline__ void cp_wait1() { asm volatile("cp.async.wait_group 1;"); }
__device__ __forceinline__ void split2(float x0, float x1,
                                       __nv_bfloat162& hi, __nv_bfloat162& lo) {
    __nv_bfloat16 h0 = __float2bfloat16_rn(x0);
    __nv_bfloat16 h1 = __float2bfloat16_rn(x1);
    hi = __nv_bfloat162(h0, h1);
    lo = __nv_bfloat162(__float2bfloat16_rn(x0 - __bfloat162float(h0)),
                        __float2bfloat16_rn(x1 - __bfloat162float(h1)));
}

// ---------------- node embedding + stats zero + deg zero ----------------------
__global__ void embed_kernel(const int* __restrict__ x,
                             const float* __restrict__ atom_emb) {
    int idx = blockIdx.x * blockDim.x + threadIdx.x;
    if (idx < 2 * D2) g_stats1[idx] = 0.f;
    if (idx < 2 * D)  g_stats2[idx] = 0.f;
    if (idx < N_NODES) g_deg[idx] = 0;
    int node = idx >> 5, lane = idx & 31;
    if (node >= N_NODES) return;
    const int* xr = x + node * 9;
    float4 acc = make_float4(0.f, 0.f, 0.f, 0.f);
#pragma unroll
    for (int f = 0; f < 9; f++) {
        int v = __ldg(xr + f);
        float4 t = ((const float4*)(atom_emb + (size_t)(f * 64 + v) * D))[lane];
        acc.x += t.x; acc.y += t.y; acc.z += t.z; acc.w += t.w;
    }
    ((float4*)(g_h + (size_t)node * D))[lane] = acc;
}

// ---------------- combined bond table ----------------------------------------
__global__ void bond_table_kernel(const float* __restrict__ bond_emb) {
    int wid = (blockIdx.x * blockDim.x + threadIdx.x) >> 5;
    int lane = threadIdx.x & 31;
    if (wid >= NLAYERS * 512) return;
    int l = wid >> 9, combo = wid & 511;
    int a0 = combo & 7, a1 = (combo >> 3) & 7, a2 = combo >> 6;
    const float* be = bond_emb + (size_t)l * 3 * 8 * D;
    float4 v0 = ((const float4*)(be + a0 * D))[lane];
    float4 v1 = ((const float4*)(be + (8 + a1) * D))[lane];
    float4 v2 = ((const float4*)(be + (16 + a2) * D))[lane];
    float4 s;
    s.x = v0.x + v1.x + v2.x;
    s.y = v0.y + v1.y + v2.y;
    s.z = v0.z + v1.z + v2.z;
    s.w = v0.w + v1.w + v2.w;
    ((float4*)(g_bond_tab + (size_t)wid * D))[lane] = s;
}

// ---------------- CSR build ---------------------------------------------------
__global__ void hist_kernel(const int* __restrict__ edge_index) {
    int e = blockIdx.x * blockDim.x + threadIdx.x;
    if (e >= N_EDGES) return;
    atomicAdd(&g_deg[__ldg(edge_index + N_EDGES + e)], 1);
}
__global__ void scan_kernel() {
    __shared__ int part[1024];
    const int CH = (N_NODES + 1023) / 1024;
    int t = threadIdx.x;
    int base = t * CH;
    int hi = min(base + CH, N_NODES);
    int s = 0;
    for (int i = base; i < hi; i++) s += g_deg[i];
    part[t] = s;
    __syncthreads();
    for (int off = 1; off < 1024; off <<= 1) {
        int v = (t >= off) ? part[t - off] : 0;
        __syncthreads();
        part[t] += v;
        __syncthreads();
    }
    int run = (t > 0) ? part[t - 1] : 0;
    for (int i = base; i < hi; i++) {
        g_rowptr[i] = run;
        g_woff[i] = run;
        run += g_deg[i];
    }
    if (t == 1023) g_rowptr[N_NODES] = part[1023];
}
__global__ void scatter_kernel(const int* __restrict__ edge_index,
                               const int* __restrict__ edge_attr,
                               const float* __restrict__ edge_weight) {
    int e = blockIdx.x * blockDim.x + threadIdx.x;
    if (e >= N_EDGES) return;
    int s = __ldg(edge_index + e);
    int d = __ldg(edge_index + N_EDGES + e);
    int a0 = __ldg(edge_attr + e * 3 + 0);
    int a1 = __ldg(edge_attr + e * 3 + 1);
    int a2 = __ldg(edge_attr + e * 3 + 2);
    uint32_t combo = (uint32_t)(a0 + (a1 << 3) + (a2 << 6));
    int pos = atomicAdd(&g_woff[d], 1);
    g_edge[pos] = make_uint2((uint32_t)s | (combo << 17),
                             __float_as_uint(__ldg(edge_weight + e)));
}

// ---- CSR aggregation -> writes PRE-SPLIT bf16 hi/lo z; re-zeroes stats ------
__global__ void agg_kernel(const float* __restrict__ eps_p, int l) {
    cudaGridDependencySynchronize();   // PDL: wait for bn_apply(l-1) / scatter
    int t = blockIdx.x * blockDim.x + threadIdx.x;
    if (t < 2 * D2) g_stats1[t] = 0.f;
    if (t < 2 * D)  g_stats2[t] = 0.f;
    int gw = t >> 5;
    int lane = threadIdx.x & 31;
    if (gw >= N_NODES) return;
    const float* tab = g_bond_tab + (size_t)l * 512 * D;
    float s = 1.f + __ldg(eps_p + l);
    float4 acc = ((const float4*)(g_h + (size_t)gw * D))[lane];
    acc.x *= s; acc.y *= s; acc.z *= s; acc.w *= s;
    int beg = __ldg(&g_rowptr[gw]);
    int end = __ldg(&g_rowptr[gw + 1]);
    for (int e = beg; e < end; e++) {
        uint2 md = __ldg(&g_edge[e]);
        int src = md.x & 0x1FFFF;
        int combo = md.x >> 17;
        float w = __uint_as_float(md.y);
        float4 hv = __ldg(((const float4*)(g_h + (size_t)src * D)) + lane);
        float4 ev = __ldg(((const float4*)(tab + (size_t)combo * D)) + lane);
        acc.x += fmaxf(hv.x + ev.x, 0.f) * w;
        acc.y += fmaxf(hv.y + ev.y, 0.f) * w;
        acc.z += fmaxf(hv.z + ev.z, 0.f) * w;
        acc.w += fmaxf(hv.w + ev.w, 0.f) * w;
    }
    __nv_bfloat162 h0, l0, h1, l1;
    split2(acc.x, acc.y, h0, l0);
    split2(acc.z, acc.w, h1, l1);
    __nv_bfloat162* zh = (__nv_bfloat162*)(g_zh + (size_t)gw * D);
    __nv_bfloat162* zl = (__nv_bfloat162*)(g_zl + (size_t)gw * D);
    zh[lane * 2] = h0; zh[lane * 2 + 1] = h1;
    zl[lane * 2] = l0; zl[lane * 2 + 1] = l1;
}

// ---- fp32 -> bf16 hi/lo split for BOTH weight tensors (one launch) ----------
__global__ void split_w_kernel(const float* __restrict__ W1,
                               const float* __restrict__ W2,
                               __nv_bfloat16* __restrict__ d1h, __nv_bfloat16* __restrict__ d1l,
                               __nv_bfloat16* __restrict__ d2h, __nv_bfloat16* __restrict__ d2l,
                               int n4) {
    int i = blockIdx.x * blockDim.x + threadIdx.x;
    const float* src;
    __nv_bfloat16 *dh, *dl;
    int j = i;
    if (i < n4) { src = W1; dh = d1h; dl = d1l; }
    else if (i < 2 * n4) { j = i - n4; src = W2; dh = d2h; dl = d2l; }
    else return;
    float4 v = ((const float4*)src)[j];
    __nv_bfloat162 h0, l0, h1, l1;
    split2(v.x, v.y, h0, l0);
    split2(v.z, v.w, h1, l1);
    ((__nv_bfloat162*)dh)[j * 2]     = h0;
    ((__nv_bfloat162*)dh)[j * 2 + 1] = h1;
    ((__nv_bfloat162*)dl)[j * 2]     = l0;
    ((__nv_bfloat162*)dl)[j * 2 + 1] = l1;
}

// ---------------- common tile geometry ---------------------------------------
#define A_STRIDE 40
#define B_STRIDE 136
#define GBM 128
#define GBN 128
#define GBK 32
#define A_BYTES (GBM * A_STRIDE * 2)
#define B_BYTES (GBK * B_STRIDE * 2)
#define STAGE_BYTES (2 * A_BYTES + 2 * B_BYTES)
#define SMEM_GEMM (2 * STAGE_BYTES)

// ======== GEMM variant 1: all-presplit inputs (A and B bf16 hi/lo, cp.async) =
template <int K, int NOUT>
__global__ __launch_bounds__(256, 2)
void gemm_presplit_kernel(const __nv_bfloat16* __restrict__ Ah_g,
                          const __nv_bfloat16* __restrict__ Al_g,
                          const __nv_bfloat16* __restrict__ Bh_g,
                          const __nv_bfloat16* __restrict__ Bl_g,
                          const float* __restrict__ bias, float* __restrict__ C,
                          float* __restrict__ stats) {
    const int NT = K / GBK;
    extern __shared__ __align__(16) char smem[];
    __shared__ float ssum[GBN], ssq[GBN];

    int tid = threadIdx.x;
    int lane = tid & 31, warp = tid >> 5;
    int wm = warp & 1, wn = warp >> 1;
    int rowBase = blockIdx.y * GBM;
    int colBase = blockIdx.x * GBN;

    if (tid < GBN) { ssum[tid] = 0.f; ssq[tid] = 0.f; }

    float acc[4][4][4];
#pragma unroll
    for (int i = 0; i < 4; i++)
#pragma unroll
        for (int j = 0; j < 4; j++)
#pragma unroll
            for (int q = 0; q < 4; q++) acc[i][j][q] = 0.f;

    auto pA_h = [&](int s) { return (__nv_bfloat16*)(smem + s * STAGE_BYTES); };
    auto pA_l = [&](int s) { return (__nv_bfloat16*)(smem + s * STAGE_BYTES + A_BYTES); };
    auto pB_h = [&](int s) { return (__nv_bfloat16*)(smem + s * STAGE_BYTES + 2 * A_BYTES); };
    auto pB_l = [&](int s) { return (__nv_bfloat16*)(smem + s * STAGE_BYTES + 2 * A_BYTES + B_BYTES); };

    auto LOADS_B = [&](int kt, int s) {
#pragma unroll
        for (int i = 0; i < 2; i++) {
            int id = tid + i * 256;
            int r = id >> 4, c = (id & 15) * 8;
            cp_async16(smem_u32(pB_h(s) + r * B_STRIDE + c),
                       Bh_g + (size_t)(kt + r) * NOUT + colBase + c, 16);
            cp_async16(smem_u32(pB_l(s) + r * B_STRIDE + c),
                       Bl_g + (size_t)(kt + r) * NOUT + colBase + c, 16);
        }
    };
    auto LOADS_A = [&](int kt, int s) {
#pragma unroll
        for (int i = 0; i < 2; i++) {
            int id = tid + i * 256;
            int r = id >> 2, c = (id & 3) * 8;
            int grow = rowBase + r;
            int sz = (grow < N_NODES) ? 16 : 0;
            cp_async16(smem_u32(pA_h(s) + r * A_STRIDE + c),
                       Ah_g + (size_t)grow * K + kt + c, sz);
            cp_async16(smem_u32(pA_l(s) + r * A_STRIDE + c),
                       Al_g + (size_t)grow * K + kt + c, sz);
        }
    };

    int lr = lane & 15;
    int lc = (lane >> 4) << 3;

    // PDL: weight loads are predecessor-independent; issue before the grid sync.
    LOADS_B(0, 0);
    cudaGridDependencySynchronize();   // wait for agg to finish writing zh/zl
    LOADS_A(0, 0);
    cp_commit();

#pragma unroll 1
    for (int t = 0; t < NT; t++) {
        int s = t & 1;
        if (t + 1 < NT) {
            LOADS_B((t + 1) * GBK, s ^ 1);
            LOADS_A((t + 1) * GBK, s ^ 1);
            cp_commit();
            cp_wait1();
        } else {
            cp_wait0();
        }
        __syncthreads();

        const __nv_bfloat16* Ahs = pA_h(s);
        const __nv_bfloat16* Als = pA_l(s);
        const __nv_bfloat16* Bhs = pB_h(s);
        const __nv_bfloat16* Bls = pB_l(s);
#pragma unroll
        for (int ks = 0; ks < GBK; ks += 16) {
            uint32_t bh[4][2], bl[4][2];
#pragma unroll
            for (int nb = 0; nb < 2; nb++) {
                int ncol = wn * 32 + nb * 16 + lc;
                uint32_t r0, r1, r2, r3;
                ldsm4t(smem_u32(Bhs + (ks + lr) * B_STRIDE + ncol), r0, r1, r2, r3);
                bh[nb * 2][0] = r0; bh[nb * 2][1] = r1;
                bh[nb * 2 + 1][0] = r2; bh[nb * 2 + 1][1] = r3;
                ldsm4t(smem_u32(Bls + (ks + lr) * B_STRIDE + ncol), r0, r1, r2, r3);
                bl[nb * 2][0] = r0; bl[nb * 2][1] = r1;
                bl[nb * 2 + 1][0] = r2; bl[nb * 2 + 1][1] = r3;
            }
#pragma unroll
            for (int mf = 0; mf < 4; mf++) {
                int mrow = wm * 64 + mf * 16 + lr;
                uint32_t ah[4], al[4];
                ldsm4(smem_u32(Ahs + mrow * A_STRIDE + ks + lc), ah[0], ah[1], ah[2], ah[3]);
                ldsm4(smem_u32(Als + mrow * A_STRIDE + ks + lc), al[0], al[1], al[2], al[3]);
#pragma unroll
                for (int nf = 0; nf < 4; nf++) {
                    mma16816(acc[mf][nf], ah, bh[nf]);
                    mma16816(acc[mf][nf], ah, bl[nf]);
                    mma16816(acc[mf][nf], al, bh[nf]);
                }
            }
        }
        __syncthreads();
    }

    int crow = lane >> 2;
    int ccol = (lane & 3) * 2;
    float bcol8[4][2];
#pragma unroll
    for (int nf = 0; nf < 4; nf++) {
        bcol8[nf][0] = bias[colBase + wn * 32 + nf * 8 + ccol];
        bcol8[nf][1] = bias[colBase + wn * 32 + nf * 8 + ccol + 1];
    }
    float psum[4][2] = {}, psq[4][2] = {};
#pragma unroll
    for (int mf = 0; mf < 4; mf++)
#pragma unroll
        for (int r2 = 0; r2 < 2; r2++) {
            int r = rowBase + wm * 64 + mf * 16 + crow + r2 * 8;
            if (r < N_NODES) {
#pragma unroll
                for (int nf = 0; nf < 4; nf++) {
                    float v0 = acc[mf][nf][r2 * 2 + 0] + bcol8[nf][0];
                    float v1 = acc[mf][nf][r2 * 2 + 1] + bcol8[nf][1];
                    *(float2*)(C + (size_t)r * NOUT + colBase + wn * 32 + nf * 8 + ccol) =
                        make_float2(v0, v1);
                    psum[nf][0] += v0; psq[nf][0] += v0 * v0;
                    psum[nf][1] += v1; psq[nf][1] += v1 * v1;
                }
            }
        }
    __syncthreads();
#pragma unroll
    for (int nf = 0; nf < 4; nf++) {
        int c = wn * 32 + nf * 8 + ccol;
        atomicAdd(&ssum[c],     psum[nf][0]);
        atomicAdd(&ssum[c + 1], psum[nf][1]);
        atomicAdd(&ssq[c],      psq[nf][0]);
        atomicAdd(&ssq[c + 1],  psq[nf][1]);
    }
    __syncthreads();
    if (tid < GBN) {
        atomicAdd(&stats[colBase + tid], ssum[tid]);
        atomicAdd(&stats[NOUT + colBase + tid], ssq[tid]);
    }
}

// ======== GEMM variant 2: fused BN1+relu+split on fp32 A (GEMM2) =============
template <int K, int NOUT>
__global__ __launch_bounds__(256, 2)
void gemm_fused_kernel(const float* __restrict__ A,
                       const __nv_bfloat16* __restrict__ Bh_g,
                       const __nv_bfloat16* __restrict__ Bl_g,
                       const float* __restrict__ bias, float* __restrict__ C,
                       const float* __restrict__ stats_in,
                       const float* __restrict__ bng, const float* __restrict__ bnb,
                       float* __restrict__ stats) {
    const int NT = K / GBK;
    extern __shared__ __align__(16) char smem[];
    __shared__ float ssum[GBN], ssq[GBN];
    __shared__ __align__(16) float s_sc[K], s_sh[K];

    int tid = threadIdx.x;
    int lane = tid & 31, warp = tid >> 5;
    int wm = warp & 1, wn = warp >> 1;
    int rowBase = blockIdx.y * GBM;
    int colBase = blockIdx.x * GBN;

    auto pA_h = [&](int s) { return (__nv_bfloat16*)(smem + s * STAGE_BYTES); };
    auto pA_l = [&](int s) { return (__nv_bfloat16*)(smem + s * STAGE_BYTES + A_BYTES); };
    auto pB_h = [&](int s) { return (__nv_bfloat16*)(smem + s * STAGE_BYTES + 2 * A_BYTES); };
    auto pB_l = [&](int s) { return (__nv_bfloat16*)(smem + s * STAGE_BYTES + 2 * A_BYTES + B_BYTES); };

    auto LOAD_B = [&](int kt, int s) {
#pragma unroll
        for (int i = 0; i < 2; i++) {
            int id = tid + i * 256;
            int r = id >> 4, c = (id & 15) * 8;
            cp_async16(smem_u32(pB_h(s) + r * B_STRIDE + c),
                       Bh_g + (size_t)(kt + r) * NOUT + colBase + c, 16);
            cp_async16(smem_u32(pB_l(s) + r * B_STRIDE + c),
                       Bl_g + (size_t)(kt + r) * NOUT + colBase + c, 16);
        }
    };

    if (tid < GBN) { ssum[tid] = 0.f; ssq[tid] = 0.f; }

    // PDL: weights are predecessor-independent
    LOAD_B(0, 0);
    cudaGridDependencySynchronize();   // wait for gemm1 (y1 + stats1)

    if (tid < K) {
        const float invn = 1.f / (float)N_NODES;
        float m = stats_in[tid] * invn;
        float var = stats_in[K + tid] * invn - m * m;
        float sc = bng[tid] * rsqrtf(var + 1e-5f);
        s_sc[tid] = sc;
        s_sh[tid] = bnb[tid] - m * sc;
    }
    __syncthreads();

    float acc[4][4][4];
#pragma unroll
    for (int i = 0; i < 4; i++)
#pragma unroll
        for (int j = 0; j < 4; j++)
#pragma unroll
            for (int q = 0; q < 4; q++) acc[i][j][q] = 0.f;

    int ar  = tid >> 1;
    int acb = (tid & 1) * 16;
    int agrow = rowBase + ar;
    bool arow_ok = (agrow < N_NODES);

    float4 areg[4];

    auto LOAD_A = [&](int kt) {
        if (arow_ok) {
            const float* ap = A + (size_t)agrow * K + kt + acb;
            areg[0] = *(const float4*)(ap + 0);
            areg[1] = *(const float4*)(ap + 4);
            areg[2] = *(const float4*)(ap + 8);
            areg[3] = *(const float4*)(ap + 12);
#pragma unroll
            for (int j = 0; j < 4; j++) {
                float4 sc = *(const float4*)(s_sc + kt + acb + j * 4);
                float4 sh = *(const float4*)(s_sh + kt + acb + j * 4);
                areg[j].x = fmaxf(fmaf(areg[j].x, sc.x, sh.x), 0.f);
                areg[j].y = fmaxf(fmaf(areg[j].y, sc.y, sh.y), 0.f);
                areg[j].z = fmaxf(fmaf(areg[j].z, sc.z, sh.z), 0.f);
                areg[j].w = fmaxf(fmaf(areg[j].w, sc.w, sh.w), 0.f);
            }
        } else {
            float4 z4 = make_float4(0.f, 0.f, 0.f, 0.f);
            areg[0] = z4; areg[1] = z4; areg[2] = z4; areg[3] = z4;
        }
    };
    auto STORE_A = [&](int s) {
        __nv_bfloat16* dh = pA_h(s) + ar * A_STRIDE + acb;
        __nv_bfloat16* dl = pA_l(s) + ar * A_STRIDE + acb;
#pragma unroll
        for (int j = 0; j < 4; j++) {
            __nv_bfloat162 h0, l0, h1, l1;
            split2(areg[j].x, areg[j].y, h0, l0);
            split2(areg[j].z, areg[j].w, h1, l1);
            *(__nv_bfloat162*)(dh + j * 4)     = h0;
            *(__nv_bfloat162*)(dh + j * 4 + 2) = h1;
            *(__nv_bfloat162*)(dl + j * 4)     = l0;
            *(__nv_bfloat162*)(dl + j * 4 + 2) = l1;
        }
    };

    int lr = lane & 15;
    int lc = (lane >> 4) << 3;

    cp_commit();                // commit B(0)
    LOAD_A(0);
    STORE_A(0);
    cp_wait0();
    __syncthreads();

    int buf = 0;
#pragma unroll 1
    for (int t = 0; t < NT; t++) {
        if (t + 1 < NT) {
            LOAD_B((t + 1) * GBK, buf ^ 1);
            cp_commit();
            LOAD_A((t + 1) * GBK);
        }

        const __nv_bfloat16* Ahs = pA_h(buf);
        const __nv_bfloat16* Als = pA_l(buf);
        const __nv_bfloat16* Bhs = pB_h(buf);
        const __nv_bfloat16* Bls = pB_l(buf);
#pragma unroll
        for (int ks = 0; ks < GBK; ks += 16) {
            uint32_t bh[4][2], bl[4][2];
#pragma unroll
            for (int nb = 0; nb < 2; nb++) {
                int ncol = wn * 32 + nb * 16 + lc;
                uint32_t r0, r1, r2, r3;
                ldsm4t(smem_u32(Bhs + (ks + lr) * B_STRIDE + ncol), r0, r1, r2, r3);
                bh[nb * 2][0] = r0; bh[nb * 2][1] = r1;
                bh[nb * 2 + 1][0] = r2; bh[nb * 2 + 1][1] = r3;
                ldsm4t(smem_u32(Bls + (ks + lr) * B_STRIDE + ncol), r0, r1, r2, r3);
                bl[nb * 2][0] = r0; bl[nb * 2][1] = r1;
                bl[nb * 2 + 1][0] = r2; bl[nb * 2 + 1][1] = r3;
            }
#pragma unroll
            for (int mf = 0; mf < 4; mf++) {
                int mrow = wm * 64 + mf * 16 + lr;
                uint32_t ah[4], al[4];
                ldsm4(smem_u32(Ahs + mrow * A_STRIDE + ks + lc), ah[0], ah[1], ah[2], ah[3]);
                ldsm4(smem_u32(Als + mrow * A_STRIDE + ks + lc), al[0], al[1], al[2], al[3]);
#pragma unroll
                for (int nf = 0; nf < 4; nf++) {
                    mma16816(acc[mf][nf], ah, bh[nf]);
                    mma16816(acc[mf][nf], ah, bl[nf]);
                    mma16816(acc[mf][nf], al, bh[nf]);
                }
            }
        }

        if (t + 1 < NT) {
            STORE_A(buf ^ 1);
            cp_wait0();
            __syncthreads();
            buf ^= 1;
        }
    }

    int crow = lane >> 2;
    int ccol = (lane & 3) * 2;
    float bcol8[4][2];
#pragma unroll
    for (int nf = 0; nf < 4; nf++) {
        bcol8[nf][0] = bias[colBase + wn * 32 + nf * 8 + ccol];
        bcol8[nf][1] = bias[colBase + wn * 32 + nf * 8 + ccol + 1];
    }
    float psum[4][2] = {}, psq[4][2] = {};
#pragma unroll
    for (int mf = 0; mf < 4; mf++)
#pragma unroll
        for (int r2 = 0; r2 < 2; r2++) {
            int r = rowBase + wm * 64 + mf * 16 + crow + r2 * 8;
            if (r < N_NODES) {
#pragma unroll
                for (int nf = 0; nf < 4; nf++) {
                    float v0 = acc[mf][nf][r2 * 2 + 0] + bcol8[nf][0];
                    float v1 = acc[mf][nf][r2 * 2 + 1] + bcol8[nf][1];
                    *(float2*)(C + (size_t)r * NOUT + colBase + wn * 32 + nf * 8 + ccol) =
                        make_float2(v0, v1);
                    psum[nf][0] += v0; psq[nf][0] += v0 * v0;
                    psum[nf][1] += v1; psq[nf][1] += v1 * v1;
                }
            }
        }
    __syncthreads();
#pragma unroll
    for (int nf = 0; nf < 4; nf++) {
        int c = wn * 32 + nf * 8 + ccol;
        atomicAdd(&ssum[c],     psum[nf][0]);
        atomicAdd(&ssum[c + 1], psum[nf][1]);
        atomicAdd(&ssq[c],      psq[nf][0]);
        atomicAdd(&ssq[c + 1],  psq[nf][1]);
    }
    __syncthreads();
    if (tid < GBN) {
        atomicAdd(&stats[colBase + tid], ssum[tid]);
        atomicAdd(&stats[NOUT + colBase + tid], ssq[tid]);
    }
}

// ------- apply BN2 (fused finalize in prologue); write h or final out --------
__global__ void bn_apply_kernel(float* __restrict__ final_out,
                                const float* __restrict__ bng,
                                const float* __restrict__ bnb, int l) {
    __shared__ __align__(16) float s_sc[D], s_sh[D];
    cudaGridDependencySynchronize();   // PDL: wait for gemm2 (z + stats2)
    int tid = threadIdx.x;
    if (tid < D) {
        const float invn = 1.f / (float)N_NODES;
        float m = g_stats2[tid] * invn;
        float var = g_stats2[D + tid] * invn - m * m;
        float sc = bng[tid] * rsqrtf(var + 1e-5f);
        s_sc[tid] = sc;
        s_sh[tid] = bnb[tid] - m * sc;
    }
    __syncthreads();
    int idx = blockIdx.x * blockDim.x + tid;
    if (idx >= N_NODES * (D / 4)) return;
    int c4 = idx & 31;
    float4 v = ((const float4*)g_z)[idx];
    float4 sc = ((const float4*)s_sc)[c4];
    float4 sh = ((const float4*)s_sh)[c4];
    v.x = fmaf(v.x, sc.x, sh.x);
    v.y = fmaf(v.y, sc.y, sh.y);
    v.z = fmaf(v.z, sc.z, sh.z);
    v.w = fmaf(v.w, sc.w, sh.w);
    if (l < NLAYERS - 1) {
        v.x = fmaxf(v.x, 0.f); v.y = fmaxf(v.y, 0.f);
        v.z = fmaxf(v.z, 0.f); v.w = fmaxf(v.w, 0.f);
        ((float4*)g_h)[idx] = v;
    } else {
        ((float4*)final_out)[idx] = v;
    }
}

// ---------------- launcher ---------------------------------------------------
extern "C" void kernel_launch(void* const* d_in, const int* in_sizes, int n_in,
                              void* d_out, int out_size) {
    const int*   x           = (const int*)d_in[0];
    const int*   edge_index  = (const int*)d_in[1];
    const int*   edge_attr   = (const int*)d_in[2];
    const float* edge_weight = (const float*)d_in[3];
    const float* atom_emb    = (const float*)d_in[4];
    const float* bond_emb    = (const float*)d_in[5];
    const float* W1          = (const float*)d_in[6];
    const float* b1          = (const float*)d_in[7];
    const float* bn1_g       = (const float*)d_in[8];
    const float* bn1_b       = (const float*)d_in[9];
    const float* W2          = (const float*)d_in[10];
    const float* b2          = (const float*)d_in[11];
    const float* eps_p       = (const float*)d_in[12];
    const float* bn_g        = (const float*)d_in[13];
    const float* bn_b        = (const float*)d_in[14];
    float* out = (float*)d_out;

    float *p_z, *p_y1, *p_st1, *p_st2;
    __nv_bfloat16 *p_zh, *p_zl, *p_w1h, *p_w1l, *p_w2h, *p_w2l;
    cudaGetSymbolAddress((void**)&p_z,   g_z);
    cudaGetSymbolAddress((void**)&p_y1,  g_y1);
    cudaGetSymbolAddress((void**)&p_st1, g_stats1);
    cudaGetSymbolAddress((void**)&p_st2, g_stats2);
    cudaGetSymbolAddress((void**)&p_zh,  g_zh);
    cudaGetSymbolAddress((void**)&p_zl,  g_zl);
    cudaGetSymbolAddress((void**)&p_w1h, g_w1h);
    cudaGetSymbolAddress((void**)&p_w1l, g_w1l);
    cudaGetSymbolAddress((void**)&p_w2h, g_w2h);
    cudaGetSymbolAddress((void**)&p_w2l, g_w2l);

    cudaFuncSetAttribute(gemm_presplit_kernel<D, D2>,
                         cudaFuncAttributeMaxDynamicSharedMemorySize, SMEM_GEMM);
    cudaFuncSetAttribute(gemm_fused_kernel<D2, D>,
                         cudaFuncAttributeMaxDynamicSharedMemorySize, SMEM_GEMM);

    const int ELT_BLOCKS = (N_NODES * (D / 4) + 255) / 256;
    const int MB = (N_NODES + GBM - 1) / GBM;
    const int WN4 = NLAYERS * D * D2 / 4;
    const int EB = (N_EDGES + 255) / 256;

    embed_kernel<<<(N_NODES * 32 + 255) / 256, 256>>>(x, atom_emb);
    bond_table_kernel<<<(NLAYERS * 512 * 32 + 255) / 256, 256>>>(bond_emb);
    split_w_kernel<<<(2 * WN4 + 255) / 256, 256>>>(W1, W2, p_w1h, p_w1l,
                                                   p_w2h, p_w2l, WN4);
    hist_kernel<<<EB, 256>>>(edge_index);
    scan_kernel<<<1, 1024>>>();
    scatter_kernel<<<EB, 256>>>(edge_index, edge_attr, edge_weight);

    // PDL launch config (consumer kernels overlap predecessor tails)
    cudaLaunchAttribute pdl_attr[1];
    pdl_attr[0].id = cudaLaunchAttributeProgrammaticStreamSerialization;
    pdl_attr[0].val.programmaticStreamSerializationAllowed = 1;

    for (int l = 0; l < NLAYERS; l++) {
        {
            cudaLaunchConfig_t cfg = {};
            cfg.gridDim = dim3((N_NODES * 32 + 255) / 256);
            cfg.blockDim = dim3(256);
            cfg.attrs = pdl_attr; cfg.numAttrs = 1;
            cudaLaunchKernelEx(&cfg, agg_kernel, eps_p, l);
        }
        {
            cudaLaunchConfig_t cfg = {};
            cfg.gridDim = dim3(D2 / GBN, MB);
            cfg.blockDim = dim3(256);
            cfg.dynamicSmemBytes = SMEM_GEMM;
            cfg.attrs = pdl_attr; cfg.numAttrs = 1;
            cudaLaunchKernelEx(&cfg, gemm_presplit_kernel<D, D2>,
                               (const __nv_bfloat16*)p_zh, (const __nv_bfloat16*)p_zl,
                               (const __nv_bfloat16*)(p_w1h + (size_t)l * D * D2),
                               (const __nv_bfloat16*)(p_w1l + (size_t)l * D * D2),
                               b1 + (size_t)l * D2, p_y1, p_st1);
        }
        {
            cudaLaunchConfig_t cfg = {};
            cfg.gridDim = dim3(D / GBN, MB);
            cfg.blockDim = dim3(256);
            cfg.dynamicSmemBytes = SMEM_GEMM;
            cfg.attrs = pdl_attr; cfg.numAttrs = 1;
            cudaLaunchKernelEx(&cfg, gemm_fused_kernel<D2, D>,
                               (const float*)p_y1,
                               (const __nv_bfloat16*)(p_w2h + (size_t)l * D2 * D),
                               (const __nv_bfloat16*)(p_w2l + (size_t)l * D2 * D),
                               b2 + (size_t)l * D, p_z, (const float*)p_st1,
                               bn1_g + (size_t)l * D2, bn1_b + (size_t)l * D2, p_st2);
        }
        {
            cudaLaunchConfig_t cfg = {};
            cfg.gridDim = dim3(ELT_BLOCKS);
            cfg.blockDim = dim3(256);
            cfg.attrs = pdl_attr; cfg.numAttrs = 1;
            cudaLaunchKernelEx(&cfg, bn_apply_kernel, out,
                               bn_g + (size_t)l * D, bn_b + (size_t)l * D, l);
        }
    }
    (void)in_sizes; (void)n_in; (void)out_size;
}